// round 11
// baseline (speedup 1.0000x reference)
#include <cuda_runtime.h>
#include <cuda_fp16.h>
#include <math.h>
#include <stdint.h>

#define NN 50000
#define EE 600000
#define ET 650000   // EE + NN (self loops appended)

// ---------------- scratch (static device memory; allocation-free) ----------------
__device__ __half2 g_xh1h[(size_t)NN * 256];   // xh1 as half2 (512 ch)
__device__ __half  g_t1h [(size_t)NN * 512];   // t1 as half
__device__ __half2 g_p1h [(size_t)NN * 256];   // p1 as half2
__device__ __half2 g_hh  [(size_t)NN * 256];   // h as half2
__device__ float   g_ew1[(size_t)ET * 64];     // logits, src-position order (fp32)
__device__ __half2 g_ew1h[(size_t)ET * 32];    // normalized attention, DST-position order, fp16
__device__ float   g_ew2[(size_t)ET * 16];     // logits layer2, src-position order
__device__ float   g_ew2d[(size_t)ET * 16];    // normalized attention layer2, DST-position order
__device__ float   g_xh2[NN * 16];
__device__ float   g_p2 [NN * 16];

__device__ int g_cnt_src[NN], g_cnt_dst[NN];
__device__ int g_ips[NN + 1], g_ipd[NN + 1];
__device__ int g_cur_src[NN], g_cur_dst[NN];
__device__ int g_eid_src[ET];
__device__ int g_ps2pd[ET];                    // src-CSR position -> dst-CSR position
__device__ int g_src_of_pd[ET];                // dst-CSR position -> src node

// ---------------- CSR build ----------------
__global__ void k_zero() {
    int i = blockIdx.x * blockDim.x + threadIdx.x;
    if (i < NN) { g_cnt_src[i] = 0; g_cnt_dst[i] = 0; }
}

__global__ void k_count(const int* __restrict__ ei) {
    int e = blockIdx.x * blockDim.x + threadIdx.x;
    if (e >= ET) return;
    int s = (e < EE) ? ei[e]      : e - EE;
    int d = (e < EE) ? ei[EE + e] : e - EE;
    atomicAdd(&g_cnt_src[s], 1);
    atomicAdd(&g_cnt_dst[d], 1);
}

__global__ void k_scan() {
    const int* cnt = (blockIdx.x == 0) ? g_cnt_src : g_cnt_dst;
    int* ip  = (blockIdx.x == 0) ? g_ips : g_ipd;
    int* cur = (blockIdx.x == 0) ? g_cur_src : g_cur_dst;
    __shared__ int wsum[32];
    int tid = threadIdx.x, lane = tid & 31, wid = tid >> 5;
    int carry = 0;
    for (int base = 0; base < NN; base += 1024) {
        int i = base + tid;
        int v = (i < NN) ? cnt[i] : 0;
        int x = v;
        #pragma unroll
        for (int o = 1; o < 32; o <<= 1) {
            int t = __shfl_up_sync(0xffffffffu, x, o);
            if (lane >= o) x += t;
        }
        if (lane == 31) wsum[wid] = x;
        __syncthreads();
        if (wid == 0) {
            int y = wsum[lane];
            #pragma unroll
            for (int o = 1; o < 32; o <<= 1) {
                int t = __shfl_up_sync(0xffffffffu, y, o);
                if (lane >= o) y += t;
            }
            wsum[lane] = y;
        }
        __syncthreads();
        int woff = (wid == 0) ? 0 : wsum[wid - 1];
        int excl = x + woff - v;
        if (i < NN) { ip[i] = carry + excl; cur[i] = carry + excl; }
        int total = wsum[31];
        __syncthreads();
        carry += total;
    }
    if (tid == 0) ip[NN] = carry;
}

__global__ void k_fill(const int* __restrict__ ei) {
    int e = blockIdx.x * blockDim.x + threadIdx.x;
    if (e >= ET) return;
    int s = (e < EE) ? ei[e]      : e - EE;
    int d = (e < EE) ? ei[EE + e] : e - EE;
    int ps = atomicAdd(&g_cur_src[s], 1);
    int pd = atomicAdd(&g_cur_dst[d], 1);
    g_eid_src[ps] = e;
    g_ps2pd[ps] = pd;
    g_src_of_pd[pd] = s;
}

// ---------------- mma helpers ----------------
__device__ __forceinline__ uint32_t f2tf32(float f) {
    uint32_t u;
    asm("cvt.rna.tf32.f32 %0, %1;" : "=r"(u) : "f"(f));
    return u;
}

__device__ __forceinline__ void mma_tf32(float* c, const uint32_t* a, uint32_t b0, uint32_t b1) {
    asm volatile(
        "mma.sync.aligned.m16n8k8.row.col.f32.tf32.tf32.f32 "
        "{%0,%1,%2,%3}, {%4,%5,%6,%7}, {%8,%9}, {%0,%1,%2,%3};"
        : "+f"(c[0]), "+f"(c[1]), "+f"(c[2]), "+f"(c[3])
        : "r"(a[0]), "r"(a[1]), "r"(a[2]), "r"(a[3]), "r"(b0), "r"(b1));
}

__device__ __forceinline__ void mma_f16(float* c, const uint32_t* a, uint32_t b0, uint32_t b1) {
    asm volatile(
        "mma.sync.aligned.m16n8k16.row.col.f32.f16.f16.f32 "
        "{%0,%1,%2,%3}, {%4,%5,%6,%7}, {%8,%9}, {%0,%1,%2,%3};"
        : "+f"(c[0]), "+f"(c[1]), "+f"(c[2]), "+f"(c[3])
        : "r"(a[0]), "r"(a[1]), "r"(a[2]), "r"(a[3]), "r"(b0), "r"(b1));
}

// ---------------- edge MLP layer1 on tensor cores (gather-staged, contiguous store) ----------------
#define ES1 136
#define EH  68
#define EB  72
#define EMLP_SMEM ((128*EH + 16*EB + 64*EB + 64 + 128) * 4)

__global__ void __launch_bounds__(256) k_emlp1(
    const float* __restrict__ KR, const float* __restrict__ w1,
    const float* __restrict__ w2, const float* __restrict__ b2,
    float* __restrict__ EW)
{
    extern __shared__ uint32_t dyn[];
    uint32_t* Hs  = dyn;
    uint32_t* As1 = dyn;
    uint32_t* Bs1 = dyn + 128 * EH;
    uint32_t* Bs2 = Bs1 + 16 * EB;
    float*    sb2 = (float*)(Bs2 + 64 * EB);
    int*      se  = (int*)(sb2 + 64);

    int tid = threadIdx.x, lane = tid & 31, wid = tid >> 5;
    int grp = lane >> 2, tig = lane & 3;
    int row0 = blockIdx.x * 128;
    int m0 = wid * 16;

    for (int i = tid; i < 16 * 64; i += 256) { int k = i >> 6, n = i & 63; Bs1[k * EB + n] = f2tf32(w1[i]); }
    for (int i = tid; i < 64 * 64; i += 256) { int k = i >> 6, n = i & 63; Bs2[k * EB + n] = f2tf32(w2[i]); }
    if (tid < 64) sb2[tid] = b2[tid];
    if (tid < 128) se[tid] = (row0 + tid < ET) ? g_eid_src[row0 + tid] : -1;
    __syncthreads();

    {
        int r = tid >> 1, q = (tid & 1) * 8;
        int e = se[r];
        float4 v0 = make_float4(0.f, 0.f, 0.f, 0.f), v1 = v0;
        if (e >= 0) {
            const float* p = KR + (size_t)e * 16 + q;
            v0 = *(const float4*)p;
            v1 = *(const float4*)(p + 4);
        }
        As1[(q + 0) * ES1 + r] = f2tf32(v0.x);
        As1[(q + 1) * ES1 + r] = f2tf32(v0.y);
        As1[(q + 2) * ES1 + r] = f2tf32(v0.z);
        As1[(q + 3) * ES1 + r] = f2tf32(v0.w);
        As1[(q + 4) * ES1 + r] = f2tf32(v1.x);
        As1[(q + 5) * ES1 + r] = f2tf32(v1.y);
        As1[(q + 6) * ES1 + r] = f2tf32(v1.z);
        As1[(q + 7) * ES1 + r] = f2tf32(v1.w);
    }
    __syncthreads();

    float acc1[8][4];
    #pragma unroll
    for (int j = 0; j < 8; j++)
        #pragma unroll
        for (int q = 0; q < 4; q++) acc1[j][q] = 0.f;
    #pragma unroll
    for (int kk = 0; kk < 16; kk += 8) {
        uint32_t a[4];
        a[0] = As1[(kk + tig) * ES1 + m0 + grp];
        a[1] = As1[(kk + tig) * ES1 + m0 + grp + 8];
        a[2] = As1[(kk + tig + 4) * ES1 + m0 + grp];
        a[3] = As1[(kk + tig + 4) * ES1 + m0 + grp + 8];
        #pragma unroll
        for (int j = 0; j < 8; j++) {
            uint32_t b0 = Bs1[(kk + tig) * EB + j * 8 + grp];
            uint32_t b1 = Bs1[(kk + tig + 4) * EB + j * 8 + grp];
            mma_tf32(acc1[j], a, b0, b1);
        }
    }
    __syncthreads();

    #pragma unroll
    for (int j = 0; j < 8; j++) {
        float c0 = acc1[j][0], c1 = acc1[j][1], c2 = acc1[j][2], c3 = acc1[j][3];
        c0 = c0 > 0.f ? c0 : 0.2f * c0;
        c1 = c1 > 0.f ? c1 : 0.2f * c1;
        c2 = c2 > 0.f ? c2 : 0.2f * c2;
        c3 = c3 > 0.f ? c3 : 0.2f * c3;
        uint2 u0 = make_uint2(f2tf32(c0), f2tf32(c1));
        uint2 u1 = make_uint2(f2tf32(c2), f2tf32(c3));
        *(uint2*)&Hs[(m0 + grp) * EH + j * 8 + 2 * tig]     = u0;
        *(uint2*)&Hs[(m0 + grp + 8) * EH + j * 8 + 2 * tig] = u1;
    }
    __syncthreads();

    float acc2[8][4];
    #pragma unroll
    for (int j = 0; j < 8; j++)
        #pragma unroll
        for (int q = 0; q < 4; q++) acc2[j][q] = 0.f;
    #pragma unroll
    for (int kk = 0; kk < 64; kk += 8) {
        uint32_t a[4];
        a[0] = Hs[(m0 + grp) * EH + kk + tig];
        a[1] = Hs[(m0 + grp + 8) * EH + kk + tig];
        a[2] = Hs[(m0 + grp) * EH + kk + tig + 4];
        a[3] = Hs[(m0 + grp + 8) * EH + kk + tig + 4];
        #pragma unroll
        for (int j = 0; j < 8; j++) {
            uint32_t b0 = Bs2[(kk + tig) * EB + j * 8 + grp];
            uint32_t b1 = Bs2[(kk + tig + 4) * EB + j * 8 + grp];
            mma_tf32(acc2[j], a, b0, b1);
        }
    }

    int r0 = row0 + m0 + grp, r1 = r0 + 8;
    #pragma unroll
    for (int j = 0; j < 8; j++) {
        int c = j * 8 + 2 * tig;
        float b0 = sb2[c], b1 = sb2[c + 1];
        if (r0 < ET) *(float2*)&EW[(size_t)r0 * 64 + c] = make_float2(acc2[j][0] + b0, acc2[j][1] + b1);
        if (r1 < ET) *(float2*)&EW[(size_t)r1 * 64 + c] = make_float2(acc2[j][2] + b0, acc2[j][3] + b1);
    }
}

// ---------------- fused small MLP (SIMT), optional gather-in ----------------
template <int IN, int HID, int OUT, int BLK, bool FACT>
__global__ void __launch_bounds__(BLK) k_mlp(
    const float* __restrict__ X, const float* __restrict__ w1,
    const float* __restrict__ w2, const float* __restrict__ b2,
    float* __restrict__ Y, int rows, const int* __restrict__ gidx)
{
    __shared__ __align__(16) float sw1[IN * HID];
    __shared__ __align__(16) float sw2[HID * OUT];
    __shared__ __align__(16) float sb[OUT];
    __shared__ float sin_[BLK * (IN + 1)];
    __shared__ float sout[BLK * OUT];
    int tid = threadIdx.x;
    for (int i = tid; i < IN * HID; i += BLK) sw1[i] = w1[i];
    for (int i = tid; i < HID * OUT; i += BLK) sw2[i] = w2[i];
    for (int i = tid; i < OUT; i += BLK) sb[i] = b2[i];
    int row0 = blockIdx.x * BLK;
    for (int i = tid; i < BLK * IN; i += BLK) {
        int r = i / IN, c = i % IN;
        int gr = row0 + r;
        float v = 0.f;
        if (gr < rows) {
            int sr = gidx ? gidx[gr] : gr;
            v = X[(size_t)sr * IN + c];
        }
        sin_[r * (IN + 1) + c] = v;
    }
    __syncthreads();
    {
        float xin[IN];
        #pragma unroll
        for (int i = 0; i < IN; i++) xin[i] = sin_[tid * (IN + 1) + i];
        float hid[HID];
        #pragma unroll
        for (int j4 = 0; j4 < HID / 4; j4++) {
            float a0 = 0, a1 = 0, a2 = 0, a3 = 0;
            #pragma unroll
            for (int i = 0; i < IN; i++) {
                float4 w = *(const float4*)&sw1[i * HID + j4 * 4];
                a0 += xin[i] * w.x; a1 += xin[i] * w.y;
                a2 += xin[i] * w.z; a3 += xin[i] * w.w;
            }
            hid[j4 * 4 + 0] = a0 > 0.f ? a0 : 0.2f * a0;
            hid[j4 * 4 + 1] = a1 > 0.f ? a1 : 0.2f * a1;
            hid[j4 * 4 + 2] = a2 > 0.f ? a2 : 0.2f * a2;
            hid[j4 * 4 + 3] = a3 > 0.f ? a3 : 0.2f * a3;
        }
        #pragma unroll
        for (int o4 = 0; o4 < OUT / 4; o4++) {
            float a0 = sb[o4 * 4 + 0], a1 = sb[o4 * 4 + 1];
            float a2 = sb[o4 * 4 + 2], a3 = sb[o4 * 4 + 3];
            #pragma unroll
            for (int j = 0; j < HID; j++) {
                float4 w = *(const float4*)&sw2[j * OUT + o4 * 4];
                float hj = hid[j];
                a0 += hj * w.x; a1 += hj * w.y; a2 += hj * w.z; a3 += hj * w.w;
            }
            if (FACT) {
                a0 = a0 > 0.f ? a0 : 0.01f * a0;
                a1 = a1 > 0.f ? a1 : 0.01f * a1;
                a2 = a2 > 0.f ? a2 : 0.01f * a2;
                a3 = a3 > 0.f ? a3 : 0.01f * a3;
            }
            sout[tid * OUT + o4 * 4 + 0] = a0;
            sout[tid * OUT + o4 * 4 + 1] = a1;
            sout[tid * OUT + o4 * 4 + 2] = a2;
            sout[tid * OUT + o4 * 4 + 3] = a3;
        }
    }
    __syncthreads();
    int nrows = rows - row0; if (nrows > BLK) nrows = BLK;
    int limit = nrows * OUT;
    for (int i = tid; i < limit; i += BLK) Y[(size_t)row0 * OUT + i] = sout[i];
}

// ---------------- segment softmax over SRC: online stats, write normalized to DST order ----------------
__global__ void k_softmax1() {
    int g = blockIdx.x * blockDim.x + threadIdx.x;
    int v = g >> 5;
    if (v >= NN) return;
    int lane = g & 31;
    int lo = g_ips[v], hi = g_ips[v + 1];
    float m0 = -1e30f, m1 = -1e30f, s0 = 0.f, s1 = 0.f;
    for (int p = lo; p < hi; p++) {
        float2 w = *(const float2*)&g_ew1[(size_t)p * 64 + 2 * lane];
        float n0 = fmaxf(m0, w.x);
        s0 = s0 * __expf(m0 - n0) + __expf(w.x - n0);
        m0 = n0;
        float n1 = fmaxf(m1, w.y);
        s1 = s1 * __expf(m1 - n1) + __expf(w.y - n1);
        m1 = n1;
    }
    float r0 = 1.f / (s0 + 1e-16f), r1 = 1.f / (s1 + 1e-16f);
    for (int p = lo; p < hi; p++) {
        float2 w = *(const float2*)&g_ew1[(size_t)p * 64 + 2 * lane];
        float a0 = __expf(w.x - m0) * r0;
        float a1 = __expf(w.y - m1) * r1;
        int pd = g_ps2pd[p];
        g_ew1h[(size_t)pd * 32 + lane] = __floats2half2_rn(a0, a1);
    }
}

__global__ void k_softmax2() {
    int g = blockIdx.x * blockDim.x + threadIdx.x;
    int v = g >> 4;
    if (v >= NN) return;
    int c = g & 15;
    int lo = g_ips[v], hi = g_ips[v + 1];
    float m = -1e30f, s = 0.f;
    for (int p = lo; p < hi; p++) {
        float w = g_ew2[(size_t)p * 16 + c];
        float n = fmaxf(m, w);
        s = s * __expf(m - n) + __expf(w - n);
        m = n;
    }
    float r = 1.f / (s + 1e-16f);
    for (int p = lo; p < hi; p++) {
        float w = g_ew2[(size_t)p * 16 + c];
        int pd = g_ps2pd[p];
        g_ew2d[(size_t)pd * 16 + c] = __expf(w - m) * r;
    }
}

// ---------------- tf32 tensor-core GEMM (kept for K=16 t1) ----------------
#define GNC 512
#define SAS 136

template <int INHALF, int OUTHALF>
__global__ void __launch_bounds__(256) k_gemm_tf32(
    const void* __restrict__ Av, const float* __restrict__ B,
    void* __restrict__ C, int M, int K,
    const float* __restrict__ bias, int act, float slope)
{
    __shared__ __align__(16) uint32_t As[2][16 * SAS];
    __shared__ __align__(16) uint32_t Bs[2][16 * SAS];

    int tid = threadIdx.x;
    int lane = tid & 31, wid = tid >> 5;
    int grp = lane >> 2, tig = lane & 3;
    int wm0 = (wid & 1) * 64, wn0 = (wid >> 1) * 32;
    int brow = blockIdx.y * 128, bcol = blockIdx.x * 128;

    int arow = tid >> 1;
    int akq  = (tid & 1) * 8;

    float acc[4][4][4];
    #pragma unroll
    for (int i = 0; i < 4; i++)
        #pragma unroll
        for (int j = 0; j < 4; j++)
            #pragma unroll
            for (int q = 0; q < 4; q++) acc[i][j][q] = 0.f;

    int KT = K >> 4;
    float4 ra0, ra1, rb0, rb1;

    auto load_tile = [&](int k0) {
        ra0 = make_float4(0.f, 0.f, 0.f, 0.f);
        ra1 = ra0;
        if (brow + arow < M) {
            if (INHALF) {
                const __half* ap = (const __half*)Av + (size_t)(brow + arow) * K + k0 + akq;
                uint4 h8 = *(const uint4*)ap;
                float2 f0 = __half22float2(*(__half2*)&h8.x);
                float2 f1 = __half22float2(*(__half2*)&h8.y);
                float2 f2 = __half22float2(*(__half2*)&h8.z);
                float2 f3 = __half22float2(*(__half2*)&h8.w);
                ra0 = make_float4(f0.x, f0.y, f1.x, f1.y);
                ra1 = make_float4(f2.x, f2.y, f3.x, f3.y);
            } else {
                const float* ap = (const float*)Av + (size_t)(brow + arow) * K + k0 + akq;
                ra0 = *(const float4*)ap;
                ra1 = *(const float4*)(ap + 4);
            }
        }
        int f0 = tid, f1 = tid + 256;
        int r0 = f0 >> 5, n0 = (f0 & 31) * 4;
        int r1 = f1 >> 5, n1 = (f1 & 31) * 4;
        rb0 = *(const float4*)&B[(size_t)(k0 + r0) * GNC + bcol + n0];
        rb1 = *(const float4*)&B[(size_t)(k0 + r1) * GNC + bcol + n1];
    };
    auto store_tile = [&](int buf) {
        As[buf][(akq + 0) * SAS + arow] = f2tf32(ra0.x);
        As[buf][(akq + 1) * SAS + arow] = f2tf32(ra0.y);
        As[buf][(akq + 2) * SAS + arow] = f2tf32(ra0.z);
        As[buf][(akq + 3) * SAS + arow] = f2tf32(ra0.w);
        As[buf][(akq + 4) * SAS + arow] = f2tf32(ra1.x);
        As[buf][(akq + 5) * SAS + arow] = f2tf32(ra1.y);
        As[buf][(akq + 6) * SAS + arow] = f2tf32(ra1.z);
        As[buf][(akq + 7) * SAS + arow] = f2tf32(ra1.w);
        int f0 = tid, f1 = tid + 256;
        int r0 = f0 >> 5, n0 = (f0 & 31) * 4;
        int r1 = f1 >> 5, n1 = (f1 & 31) * 4;
        uint4 b0 = make_uint4(f2tf32(rb0.x), f2tf32(rb0.y), f2tf32(rb0.z), f2tf32(rb0.w));
        uint4 b1 = make_uint4(f2tf32(rb1.x), f2tf32(rb1.y), f2tf32(rb1.z), f2tf32(rb1.w));
        *(uint4*)&Bs[buf][r0 * SAS + n0] = b0;
        *(uint4*)&Bs[buf][r1 * SAS + n1] = b1;
    };

    load_tile(0);
    store_tile(0);
    __syncthreads();

    for (int kt = 0; kt < KT; kt++) {
        bool has_next = (kt + 1 < KT);
        if (has_next) load_tile((kt + 1) << 4);
        int buf = kt & 1;

        #pragma unroll
        for (int ks = 0; ks < 16; ks += 8) {
            uint32_t af[4][4], bf[4][2];
            #pragma unroll
            for (int i = 0; i < 4; i++) {
                int mb = wm0 + i * 16 + grp;
                int kk = ks + tig;
                af[i][0] = As[buf][kk * SAS + mb];
                af[i][1] = As[buf][kk * SAS + mb + 8];
                af[i][2] = As[buf][(kk + 4) * SAS + mb];
                af[i][3] = As[buf][(kk + 4) * SAS + mb + 8];
            }
            #pragma unroll
            for (int j = 0; j < 4; j++) {
                int nb = wn0 + j * 8 + grp;
                int kk = ks + tig;
                bf[j][0] = Bs[buf][kk * SAS + nb];
                bf[j][1] = Bs[buf][(kk + 4) * SAS + nb];
            }
            #pragma unroll
            for (int i = 0; i < 4; i++)
                #pragma unroll
                for (int j = 0; j < 4; j++)
                    mma_tf32(acc[i][j], af[i], bf[j][0], bf[j][1]);
        }
        if (has_next) {
            store_tile((kt + 1) & 1);
            __syncthreads();
        }
    }

    #pragma unroll
    for (int i = 0; i < 4; i++) {
        int r0 = brow + wm0 + i * 16 + grp;
        #pragma unroll
        for (int j = 0; j < 4; j++) {
            int c = bcol + wn0 + j * 8 + tig * 2;
            float b0 = bias ? bias[c] : 0.f;
            float b1 = bias ? bias[c + 1] : 0.f;
            float v0 = acc[i][j][0] + b0, v1 = acc[i][j][1] + b1;
            float v2 = acc[i][j][2] + b0, v3 = acc[i][j][3] + b1;
            if (act) {
                v0 = v0 > 0.f ? v0 : slope * v0;
                v1 = v1 > 0.f ? v1 : slope * v1;
                v2 = v2 > 0.f ? v2 : slope * v2;
                v3 = v3 > 0.f ? v3 : slope * v3;
            }
            if (OUTHALF) {
                __half* Ch = (__half*)C;
                if (r0 < M)     *(__half2*)&Ch[(size_t)r0 * GNC + c]       = __floats2half2_rn(v0, v1);
                if (r0 + 8 < M) *(__half2*)&Ch[(size_t)(r0 + 8) * GNC + c] = __floats2half2_rn(v2, v3);
            } else {
                float* Cf = (float*)C;
                if (r0 < M)     *(float2*)&Cf[(size_t)r0 * GNC + c]       = make_float2(v0, v1);
                if (r0 + 8 < M) *(float2*)&Cf[(size_t)(r0 + 8) * GNC + c] = make_float2(v2, v3);
            }
        }
    }
}

// ---------------- fp16 m16n8k16 GEMM: C[M,512] = act(A[M,K]@B[K,512]+bias), K%32==0 ----------------
#define FSA 20

template <int AHALF, int OUTHALF>
__global__ void __launch_bounds__(256) k_gemm_f16(
    const void* __restrict__ Av, const float* __restrict__ B,
    void* __restrict__ C, int M, int K,
    const float* __restrict__ bias, int act, float slope)
{
    __shared__ __align__(16) uint32_t As[2][128 * FSA];
    __shared__ __align__(16) uint32_t Bs[2][128 * FSA];

    int tid = threadIdx.x;
    int lane = tid & 31, wid = tid >> 5;
    int grp = lane >> 2, tig = lane & 3;
    int wm0 = (wid & 1) * 64, wn0 = (wid >> 1) * 32;
    int brow = blockIdx.y * 128, bcol = blockIdx.x * 128;

    int am = tid >> 1, aq = tid & 1;

    float acc[4][4][4];
    #pragma unroll
    for (int i = 0; i < 4; i++)
        #pragma unroll
        for (int j = 0; j < 4; j++)
            #pragma unroll
            for (int q = 0; q < 4; q++) acc[i][j][q] = 0.f;

    int KT = K >> 5;
    uint32_t ua[8];
    float rb0[8], rb1[8];

    auto load_tile = [&](int k0) {
        if (brow + am < M) {
            if (AHALF) {
                const __half* ap = (const __half*)Av + (size_t)(brow + am) * K + k0 + 16 * aq;
                uint4 u0 = *(const uint4*)ap;
                uint4 u1 = *(const uint4*)(ap + 8);
                ua[0] = u0.x; ua[1] = u0.y; ua[2] = u0.z; ua[3] = u0.w;
                ua[4] = u1.x; ua[5] = u1.y; ua[6] = u1.z; ua[7] = u1.w;
            } else {
                const float* ap = (const float*)Av + (size_t)(brow + am) * K + k0 + 16 * aq;
                #pragma unroll
                for (int j = 0; j < 4; j++) {
                    float4 f = *(const float4*)(ap + 4 * j);
                    __half2 h0 = __floats2half2_rn(f.x, f.y);
                    __half2 h1 = __floats2half2_rn(f.z, f.w);
                    ua[2 * j]     = *(uint32_t*)&h0;
                    ua[2 * j + 1] = *(uint32_t*)&h1;
                }
            }
        } else {
            #pragma unroll
            for (int j = 0; j < 8; j++) ua[j] = 0u;
        }
        #pragma unroll
        for (int i = 0; i < 8; i++) {
            int idx = tid + 256 * i;
            int n = idx & 127, kh = idx >> 7;
            const float* bp = B + (size_t)(k0 + 2 * kh) * GNC + bcol + n;
            rb0[i] = bp[0];
            rb1[i] = bp[GNC];
        }
    };
    auto store_tile = [&](int buf) {
        #pragma unroll
        for (int j = 0; j < 8; j++) As[buf][am * FSA + 8 * aq + j] = ua[j];
        #pragma unroll
        for (int i = 0; i < 8; i++) {
            int idx = tid + 256 * i;
            int n = idx & 127, kh = idx >> 7;
            __half2 h = __floats2half2_rn(rb0[i], rb1[i]);
            Bs[buf][n * FSA + kh] = *(uint32_t*)&h;
        }
    };

    load_tile(0);
    store_tile(0);
    __syncthreads();

    for (int kt = 0; kt < KT; kt++) {
        bool has_next = (kt + 1 < KT);
        if (has_next) load_tile((kt + 1) << 5);
        int buf = kt & 1;

        #pragma unroll
        for (int ks = 0; ks < 2; ks++) {
            uint32_t af[4][4], bf[4][2];
            #pragma unroll
            for (int i = 0; i < 4; i++) {
                int m = wm0 + i * 16 + grp;
                int b0 = m * FSA + ks * 8;
                int b1 = (m + 8) * FSA + ks * 8;
                af[i][0] = As[buf][b0 + tig];
                af[i][1] = As[buf][b1 + tig];
                af[i][2] = As[buf][b0 + tig + 4];
                af[i][3] = As[buf][b1 + tig + 4];
            }
            #pragma unroll
            for (int j = 0; j < 4; j++) {
                int n = wn0 + j * 8 + grp;
                bf[j][0] = Bs[buf][n * FSA + ks * 8 + tig];
                bf[j][1] = Bs[buf][n * FSA + ks * 8 + tig + 4];
            }
            #pragma unroll
            for (int i = 0; i < 4; i++)
                #pragma unroll
                for (int j = 0; j < 4; j++)
                    mma_f16(acc[i][j], af[i], bf[j][0], bf[j][1]);
        }
        if (has_next) {
            store_tile((kt + 1) & 1);
            __syncthreads();
        }
    }

    #pragma unroll
    for (int i = 0; i < 4; i++) {
        int r0 = brow + wm0 + i * 16 + grp;
        #pragma unroll
        for (int j = 0; j < 4; j++) {
            int c = bcol + wn0 + j * 8 + tig * 2;
            float b0 = bias ? bias[c] : 0.f;
            float b1 = bias ? bias[c + 1] : 0.f;
            float v0 = acc[i][j][0] + b0, v1 = acc[i][j][1] + b1;
            float v2 = acc[i][j][2] + b0, v3 = acc[i][j][3] + b1;
            if (act) {
                v0 = v0 > 0.f ? v0 : slope * v0;
                v1 = v1 > 0.f ? v1 : slope * v1;
                v2 = v2 > 0.f ? v2 : slope * v2;
                v3 = v3 > 0.f ? v3 : slope * v3;
            }
            if (OUTHALF) {
                __half* Ch = (__half*)C;
                if (r0 < M)     *(__half2*)&Ch[(size_t)r0 * GNC + c]       = __floats2half2_rn(v0, v1);
                if (r0 + 8 < M) *(__half2*)&Ch[(size_t)(r0 + 8) * GNC + c] = __floats2half2_rn(v2, v3);
            } else {
                float* Cf = (float*)C;
                if (r0 < M)     *(float2*)&Cf[(size_t)r0 * GNC + c]       = make_float2(v0, v1);
                if (r0 + 8 < M) *(float2*)&Cf[(size_t)(r0 + 8) * GNC + c] = make_float2(v2, v3);
            }
        }
    }
}

// ---------------- layer-1 aggregation (unroll-4): streaming attention, gathered xh1h ----------------
__global__ void __launch_bounds__(256) k_agg1(
    const float* __restrict__ bias, const float* __restrict__ alphap)
{
    int g = blockIdx.x * blockDim.x + threadIdx.x;
    int v = g >> 5;
    if (v >= NN) return;
    int lane = g & 31;
    float2 acc[8];
    #pragma unroll
    for (int k = 0; k < 8; k++) acc[k] = make_float2(0.f, 0.f);
    int lo = g_ipd[v], hi = g_ipd[v + 1];
    int p = lo;
    for (; p + 3 < hi; p += 4) {
        int s0 = g_src_of_pd[p];
        int s1 = g_src_of_pd[p + 1];
        int s2 = g_src_of_pd[p + 2];
        int s3 = g_src_of_pd[p + 3];
        float2 a0 = __half22float2(g_ew1h[(size_t)p * 32 + lane]);
        float2 a1 = __half22float2(g_ew1h[(size_t)(p + 1) * 32 + lane]);
        float2 a2 = __half22float2(g_ew1h[(size_t)(p + 2) * 32 + lane]);
        float2 a3 = __half22float2(g_ew1h[(size_t)(p + 3) * 32 + lane]);
        const __half2* x0 = g_xh1h + (size_t)s0 * 256;
        const __half2* x1 = g_xh1h + (size_t)s1 * 256;
        const __half2* x2 = g_xh1h + (size_t)s2 * 256;
        const __half2* x3 = g_xh1h + (size_t)s3 * 256;
        #pragma unroll
        for (int k = 0; k < 8; k++) {
            float2 f0 = __half22float2(x0[lane + 32 * k]);
            float2 f1 = __half22float2(x1[lane + 32 * k]);
            float2 f2 = __half22float2(x2[lane + 32 * k]);
            float2 f3 = __half22float2(x3[lane + 32 * k]);
            acc[k].x += a0.x * f0.x + a1.x * f1.x + a2.x * f2.x + a3.x * f3.x;
            acc[k].y += a0.y * f0.y + a1.y * f1.y + a2.y * f2.y + a3.y * f3.y;
        }
    }
    for (; p < hi; p++) {
        int s0 = g_src_of_pd[p];
        float2 a0 = __half22float2(g_ew1h[(size_t)p * 32 + lane]);
        const __half2* x0 = g_xh1h + (size_t)s0 * 256;
        #pragma unroll
        for (int k = 0; k < 8; k++) {
            float2 f0 = __half22float2(x0[lane + 32 * k]);
            acc[k].x += a0.x * f0.x;
            acc[k].y += a0.y * f0.y;
        }
    }

    float al = *alphap;
    const __half2* pr = g_p1h + (size_t)v * 256;
    __half2* hw = g_hh + (size_t)v * 256;
    #pragma unroll
    for (int k = 0; k < 8; k++) {
        int j = 2 * lane + 64 * k;
        float2 pv = __half22float2(pr[lane + 32 * k]);
        float o0 = fmaxf(acc[k].x + bias[j]     + al * pv.x, 0.f);
        float o1 = fmaxf(acc[k].y + bias[j + 1] + al * pv.y, 0.f);
        hw[lane + 32 * k] = __floats2half2_rn(o0, o1);
    }
}

// ---------------- xh2 = h @ W_src2  ([N,512]x[512,16], h fp16) ----------------
__global__ void __launch_bounds__(256) k_xh2(const float* __restrict__ W) {
    __shared__ float sW[512 * 16];
    int tid = threadIdx.x;
    for (int i = tid; i < 512 * 16; i += 256) sW[i] = W[i];
    __syncthreads();
    int g = blockIdx.x * 256 + tid;
    int v = g >> 4, c = g & 15;
    if (v >= NN) return;
    const __half2* hr = g_hh + (size_t)v * 256;
    float acc = 0.f;
    #pragma unroll 4
    for (int i = 0; i < 256; i++) {
        float2 f = __half22float2(hr[i]);
        int j = 2 * (i & 31) + 64 * (i >> 5);
        acc += f.x * sW[j * 16 + c] + f.y * sW[(j + 1) * 16 + c];
    }
    g_xh2[g] = acc;
}

// ---------------- layer-2 aggregation + bias + alpha*p2 + log_softmax ----------------
__global__ void __launch_bounds__(256) k_agg2(
    const float* __restrict__ bias2, const float* __restrict__ alphap,
    float* __restrict__ out)
{
    int g = blockIdx.x * 256 + threadIdx.x;
    int v = g >> 4, c = g & 15;
    float acc = 0.f;
    int lo = g_ipd[v], hi = g_ipd[v + 1];
    for (int p = lo; p < hi; p++) {
        int s = g_src_of_pd[p];
        acc += g_ew2d[(size_t)p * 16 + c] * g_xh2[s * 16 + c];
    }
    float o = acc + bias2[c] + (*alphap) * g_p2[g];
    float m = o;
    #pragma unroll
    for (int d = 8; d > 0; d >>= 1) m = fmaxf(m, __shfl_xor_sync(0xffffffffu, m, d, 16));
    float se = __expf(o - m);
    #pragma unroll
    for (int d = 8; d > 0; d >>= 1) se += __shfl_xor_sync(0xffffffffu, se, d, 16);
    out[g] = o - m - logf(se);
}

// ---------------- stream/event context ----------------
struct HxCtx {
    cudaStream_t sB, sC;
    cudaEvent_t ev0, evCSR, evB, evC;
    HxCtx() {
        cudaStreamCreateWithFlags(&sB, cudaStreamNonBlocking);
        cudaStreamCreateWithFlags(&sC, cudaStreamNonBlocking);
        cudaEventCreateWithFlags(&ev0,   cudaEventDisableTiming);
        cudaEventCreateWithFlags(&evCSR, cudaEventDisableTiming);
        cudaEventCreateWithFlags(&evB,   cudaEventDisableTiming);
        cudaEventCreateWithFlags(&evC,   cudaEventDisableTiming);
        cudaFuncSetAttribute(k_emlp1, cudaFuncAttributeMaxDynamicSharedMemorySize, EMLP_SMEM);
    }
};
static HxCtx g_ctx;

// ---------------- host launch ----------------
extern "C" void kernel_launch(void* const* d_in, const int* in_sizes, int n_in,
                              void* d_out, int out_size)
{
    const float* x       = (const float*)d_in[0];
    const int*   ei      = (const int*)  d_in[1];
    const float* alpha   = (const float*)d_in[2];
    const float* k_ricci = (const float*)d_in[3];
    const float* e_poinc = (const float*)d_in[4];
    const float* W1      = (const float*)d_in[5];
    const float* h1w1    = (const float*)d_in[6];
    const float* h1w2    = (const float*)d_in[7];
    const float* h1b2    = (const float*)d_in[8];
    const float* p1w1    = (const float*)d_in[9];
    const float* p1w2    = (const float*)d_in[10];
    const float* p1b2    = (const float*)d_in[11];
    const float* bias1   = (const float*)d_in[12];
    const float* W2      = (const float*)d_in[13];
    const float* h2w1    = (const float*)d_in[14];
    const float* h2w2    = (const float*)d_in[15];
    const float* h2b2    = (const float*)d_in[16];
    const float* p2w1    = (const float*)d_in[17];
    const float* p2w2    = (const float*)d_in[18];
    const float* p2b2    = (const float*)d_in[19];
    const float* bias2   = (const float*)d_in[20];
    float* out = (float*)d_out;

    void *p_xh1h, *p_t1h, *p_p1h;
    float *p_ew1, *p_ew2, *p_p2;
    int *p_eid_src;
    cudaGetSymbolAddress(&p_xh1h, g_xh1h);
    cudaGetSymbolAddress(&p_t1h,  g_t1h);
    cudaGetSymbolAddress(&p_p1h,  g_p1h);
    cudaGetSymbolAddress((void**)&p_ew1, g_ew1);
    cudaGetSymbolAddress((void**)&p_ew2, g_ew2);
    cudaGetSymbolAddress((void**)&p_p2,  g_p2);
    cudaGetSymbolAddress((void**)&p_eid_src, g_eid_src);

    cudaStream_t sB = g_ctx.sB, sC = g_ctx.sC;

    // fork
    cudaEventRecord(g_ctx.ev0, 0);
    cudaStreamWaitEvent(sB, g_ctx.ev0, 0);
    cudaStreamWaitEvent(sC, g_ctx.ev0, 0);

    // ---- stream B: CSR + layer-1 attention (the agg1 prerequisites ONLY) ----
    k_zero<<<(NN + 255) / 256, 256, 0, sB>>>();
    k_count<<<(ET + 255) / 256, 256, 0, sB>>>(ei);
    k_scan<<<2, 1024, 0, sB>>>();
    k_fill<<<(ET + 255) / 256, 256, 0, sB>>>(ei);
    cudaEventRecord(g_ctx.evCSR, sB);
    k_emlp1<<<(ET + 127) / 128, 256, EMLP_SMEM, sB>>>(k_ricci, h1w1, h1w2, h1b2, p_ew1);
    k_softmax1<<<(NN * 32) / 256, 256, 0, sB>>>();
    cudaEventRecord(g_ctx.evB, sB);

    // ---- stream C: layer-2 attention + p2 (only needed by agg2; overlaps with agg1/xh2) ----
    cudaStreamWaitEvent(sC, g_ctx.evCSR, 0);
    k_mlp<16, 16, 16, 128, false><<<(ET + 127) / 128, 128, 0, sC>>>(k_ricci, h2w1, h2w2, h2b2, p_ew2, ET, p_eid_src);
    k_softmax2<<<(NN * 16) / 256, 256, 0, sC>>>();
    k_mlp<16, 16, 16, 128, true><<<(NN + 127) / 128, 128, 0, sC>>>(e_poinc, p2w1, p2w2, p2b2, p_p2, NN, nullptr);
    cudaEventRecord(g_ctx.evC, sC);

    // ---- default stream: dense chain (fp16 HMMA for the two big GEMMs) ----
    dim3 gg(512 / 128, (NN + 127) / 128);
    k_gemm_f16 <0, 1><<<gg, 256>>>(x,       W1,   p_xh1h, NN, 128, nullptr, 0, 0.f);
    k_gemm_tf32<0, 1><<<gg, 256>>>(e_poinc, p1w1, p_t1h,  NN, 16,  nullptr, 1, 0.2f);
    k_gemm_f16 <1, 1><<<gg, 256>>>(p_t1h,   p1w2, p_p1h,  NN, 512, p1b2,    1, 0.01f);

    // join for agg1 (needs softmax1 + xh1 + p1)
    cudaStreamWaitEvent(0, g_ctx.evB, 0);
    k_agg1<<<(NN * 32) / 256, 256>>>(bias1, alpha);
    k_xh2<<<(NN * 16) / 256, 256>>>(W2);

    // join for agg2 (needs xh2 + ew2d + p2)
    cudaStreamWaitEvent(0, g_ctx.evC, 0);
    k_agg2<<<(NN * 16) / 256, 256>>>(bias2, alpha, out);
}

// round 12
// speedup vs baseline: 1.0750x; 1.0750x over previous
#include <cuda_runtime.h>
#include <cuda_fp16.h>
#include <math.h>
#include <stdint.h>

#define NN 50000
#define EE 600000
#define ET 650000   // EE + NN (self loops appended)

// ---------------- scratch (static device memory; allocation-free) ----------------
__device__ __half2 g_xh1h[(size_t)NN * 256];   // xh1 as half2 (512 ch)
__device__ __half  g_t1h [(size_t)NN * 512];   // t1 as half
__device__ __half2 g_p1h [(size_t)NN * 256];   // p1 as half2
__device__ __half2 g_hh  [(size_t)NN * 256];   // h as half2
__device__ __half2 g_ew1l[(size_t)ET * 32];    // logits, src-position order, fp16 (half2 h = ch 2h,2h+1)
__device__ __half2 g_ew1h[(size_t)ET * 32];    // normalized attention, DST-position order, fp16
__device__ float   g_ew2[(size_t)ET * 16];     // logits layer2, src-position order
__device__ float   g_ew2d[(size_t)ET * 16];    // normalized attention layer2, DST-position order
__device__ float   g_xh2[NN * 16];
__device__ float   g_p2 [NN * 16];

__device__ int g_cnt_src[NN], g_cnt_dst[NN];
__device__ int g_ips[NN + 1], g_ipd[NN + 1];
__device__ int g_cur_src[NN], g_cur_dst[NN];
__device__ int g_eid_src[ET];
__device__ int g_ps2pd[ET];                    // src-CSR position -> dst-CSR position
__device__ int g_src_of_pd[ET];                // dst-CSR position -> src node

// ---------------- CSR build ----------------
__global__ void k_zero() {
    int i = blockIdx.x * blockDim.x + threadIdx.x;
    if (i < NN) { g_cnt_src[i] = 0; g_cnt_dst[i] = 0; }
}

__global__ void k_count(const int* __restrict__ ei) {
    int e = blockIdx.x * blockDim.x + threadIdx.x;
    if (e >= ET) return;
    int s = (e < EE) ? ei[e]      : e - EE;
    int d = (e < EE) ? ei[EE + e] : e - EE;
    atomicAdd(&g_cnt_src[s], 1);
    atomicAdd(&g_cnt_dst[d], 1);
}

__global__ void k_scan() {
    const int* cnt = (blockIdx.x == 0) ? g_cnt_src : g_cnt_dst;
    int* ip  = (blockIdx.x == 0) ? g_ips : g_ipd;
    int* cur = (blockIdx.x == 0) ? g_cur_src : g_cur_dst;
    __shared__ int wsum[32];
    int tid = threadIdx.x, lane = tid & 31, wid = tid >> 5;
    int carry = 0;
    for (int base = 0; base < NN; base += 1024) {
        int i = base + tid;
        int v = (i < NN) ? cnt[i] : 0;
        int x = v;
        #pragma unroll
        for (int o = 1; o < 32; o <<= 1) {
            int t = __shfl_up_sync(0xffffffffu, x, o);
            if (lane >= o) x += t;
        }
        if (lane == 31) wsum[wid] = x;
        __syncthreads();
        if (wid == 0) {
            int y = wsum[lane];
            #pragma unroll
            for (int o = 1; o < 32; o <<= 1) {
                int t = __shfl_up_sync(0xffffffffu, y, o);
                if (lane >= o) y += t;
            }
            wsum[lane] = y;
        }
        __syncthreads();
        int woff = (wid == 0) ? 0 : wsum[wid - 1];
        int excl = x + woff - v;
        if (i < NN) { ip[i] = carry + excl; cur[i] = carry + excl; }
        int total = wsum[31];
        __syncthreads();
        carry += total;
    }
    if (tid == 0) ip[NN] = carry;
}

__global__ void k_fill(const int* __restrict__ ei) {
    int e = blockIdx.x * blockDim.x + threadIdx.x;
    if (e >= ET) return;
    int s = (e < EE) ? ei[e]      : e - EE;
    int d = (e < EE) ? ei[EE + e] : e - EE;
    int ps = atomicAdd(&g_cur_src[s], 1);
    int pd = atomicAdd(&g_cur_dst[d], 1);
    g_eid_src[ps] = e;
    g_ps2pd[ps] = pd;
    g_src_of_pd[pd] = s;
}

// ---------------- mma helpers ----------------
__device__ __forceinline__ uint32_t f2tf32(float f) {
    uint32_t u;
    asm("cvt.rna.tf32.f32 %0, %1;" : "=r"(u) : "f"(f));
    return u;
}

__device__ __forceinline__ void mma_tf32(float* c, const uint32_t* a, uint32_t b0, uint32_t b1) {
    asm volatile(
        "mma.sync.aligned.m16n8k8.row.col.f32.tf32.tf32.f32 "
        "{%0,%1,%2,%3}, {%4,%5,%6,%7}, {%8,%9}, {%0,%1,%2,%3};"
        : "+f"(c[0]), "+f"(c[1]), "+f"(c[2]), "+f"(c[3])
        : "r"(a[0]), "r"(a[1]), "r"(a[2]), "r"(a[3]), "r"(b0), "r"(b1));
}

__device__ __forceinline__ void mma_f16(float* c, const uint32_t* a, uint32_t b0, uint32_t b1) {
    asm volatile(
        "mma.sync.aligned.m16n8k16.row.col.f32.f16.f16.f32 "
        "{%0,%1,%2,%3}, {%4,%5,%6,%7}, {%8,%9}, {%0,%1,%2,%3};"
        : "+f"(c[0]), "+f"(c[1]), "+f"(c[2]), "+f"(c[3])
        : "r"(a[0]), "r"(a[1]), "r"(a[2]), "r"(a[3]), "r"(b0), "r"(b1));
}

// ---------------- edge MLP layer1 on tensor cores (gather-staged, fp16 logits out) ----------------
#define ES1 136
#define EH  68
#define EB  72
#define EMLP_SMEM ((128*EH + 16*EB + 64*EB + 64 + 128) * 4)

__global__ void __launch_bounds__(256) k_emlp1(
    const float* __restrict__ KR, const float* __restrict__ w1,
    const float* __restrict__ w2, const float* __restrict__ b2,
    __half2* __restrict__ EW)
{
    extern __shared__ uint32_t dyn[];
    uint32_t* Hs  = dyn;
    uint32_t* As1 = dyn;
    uint32_t* Bs1 = dyn + 128 * EH;
    uint32_t* Bs2 = Bs1 + 16 * EB;
    float*    sb2 = (float*)(Bs2 + 64 * EB);
    int*      se  = (int*)(sb2 + 64);

    int tid = threadIdx.x, lane = tid & 31, wid = tid >> 5;
    int grp = lane >> 2, tig = lane & 3;
    int row0 = blockIdx.x * 128;
    int m0 = wid * 16;

    for (int i = tid; i < 16 * 64; i += 256) { int k = i >> 6, n = i & 63; Bs1[k * EB + n] = f2tf32(w1[i]); }
    for (int i = tid; i < 64 * 64; i += 256) { int k = i >> 6, n = i & 63; Bs2[k * EB + n] = f2tf32(w2[i]); }
    if (tid < 64) sb2[tid] = b2[tid];
    if (tid < 128) se[tid] = (row0 + tid < ET) ? g_eid_src[row0 + tid] : -1;
    __syncthreads();

    {
        int r = tid >> 1, q = (tid & 1) * 8;
        int e = se[r];
        float4 v0 = make_float4(0.f, 0.f, 0.f, 0.f), v1 = v0;
        if (e >= 0) {
            const float* p = KR + (size_t)e * 16 + q;
            v0 = *(const float4*)p;
            v1 = *(const float4*)(p + 4);
        }
        As1[(q + 0) * ES1 + r] = f2tf32(v0.x);
        As1[(q + 1) * ES1 + r] = f2tf32(v0.y);
        As1[(q + 2) * ES1 + r] = f2tf32(v0.z);
        As1[(q + 3) * ES1 + r] = f2tf32(v0.w);
        As1[(q + 4) * ES1 + r] = f2tf32(v1.x);
        As1[(q + 5) * ES1 + r] = f2tf32(v1.y);
        As1[(q + 6) * ES1 + r] = f2tf32(v1.z);
        As1[(q + 7) * ES1 + r] = f2tf32(v1.w);
    }
    __syncthreads();

    float acc1[8][4];
    #pragma unroll
    for (int j = 0; j < 8; j++)
        #pragma unroll
        for (int q = 0; q < 4; q++) acc1[j][q] = 0.f;
    #pragma unroll
    for (int kk = 0; kk < 16; kk += 8) {
        uint32_t a[4];
        a[0] = As1[(kk + tig) * ES1 + m0 + grp];
        a[1] = As1[(kk + tig) * ES1 + m0 + grp + 8];
        a[2] = As1[(kk + tig + 4) * ES1 + m0 + grp];
        a[3] = As1[(kk + tig + 4) * ES1 + m0 + grp + 8];
        #pragma unroll
        for (int j = 0; j < 8; j++) {
            uint32_t b0 = Bs1[(kk + tig) * EB + j * 8 + grp];
            uint32_t b1 = Bs1[(kk + tig + 4) * EB + j * 8 + grp];
            mma_tf32(acc1[j], a, b0, b1);
        }
    }
    __syncthreads();

    #pragma unroll
    for (int j = 0; j < 8; j++) {
        float c0 = acc1[j][0], c1 = acc1[j][1], c2 = acc1[j][2], c3 = acc1[j][3];
        c0 = c0 > 0.f ? c0 : 0.2f * c0;
        c1 = c1 > 0.f ? c1 : 0.2f * c1;
        c2 = c2 > 0.f ? c2 : 0.2f * c2;
        c3 = c3 > 0.f ? c3 : 0.2f * c3;
        uint2 u0 = make_uint2(f2tf32(c0), f2tf32(c1));
        uint2 u1 = make_uint2(f2tf32(c2), f2tf32(c3));
        *(uint2*)&Hs[(m0 + grp) * EH + j * 8 + 2 * tig]     = u0;
        *(uint2*)&Hs[(m0 + grp + 8) * EH + j * 8 + 2 * tig] = u1;
    }
    __syncthreads();

    float acc2[8][4];
    #pragma unroll
    for (int j = 0; j < 8; j++)
        #pragma unroll
        for (int q = 0; q < 4; q++) acc2[j][q] = 0.f;
    #pragma unroll
    for (int kk = 0; kk < 64; kk += 8) {
        uint32_t a[4];
        a[0] = Hs[(m0 + grp) * EH + kk + tig];
        a[1] = Hs[(m0 + grp + 8) * EH + kk + tig];
        a[2] = Hs[(m0 + grp) * EH + kk + tig + 4];
        a[3] = Hs[(m0 + grp + 8) * EH + kk + tig + 4];
        #pragma unroll
        for (int j = 0; j < 8; j++) {
            uint32_t b0 = Bs2[(kk + tig) * EB + j * 8 + grp];
            uint32_t b1 = Bs2[(kk + tig + 4) * EB + j * 8 + grp];
            mma_tf32(acc2[j], a, b0, b1);
        }
    }

    // fp16 logits out: half2 index h = channels (2h, 2h+1); c = j*8+2*tig -> h = j*4+tig
    int r0 = row0 + m0 + grp, r1 = r0 + 8;
    #pragma unroll
    for (int j = 0; j < 8; j++) {
        int c = j * 8 + 2 * tig;
        float b0 = sb2[c], b1 = sb2[c + 1];
        int h = j * 4 + tig;
        if (r0 < ET) EW[(size_t)r0 * 32 + h] = __floats2half2_rn(acc2[j][0] + b0, acc2[j][1] + b1);
        if (r1 < ET) EW[(size_t)r1 * 32 + h] = __floats2half2_rn(acc2[j][2] + b0, acc2[j][3] + b1);
    }
}

// ---------------- fused small MLP (SIMT), optional gather-in ----------------
template <int IN, int HID, int OUT, int BLK, bool FACT>
__global__ void __launch_bounds__(BLK) k_mlp(
    const float* __restrict__ X, const float* __restrict__ w1,
    const float* __restrict__ w2, const float* __restrict__ b2,
    float* __restrict__ Y, int rows, const int* __restrict__ gidx)
{
    __shared__ __align__(16) float sw1[IN * HID];
    __shared__ __align__(16) float sw2[HID * OUT];
    __shared__ __align__(16) float sb[OUT];
    __shared__ float sin_[BLK * (IN + 1)];
    __shared__ float sout[BLK * OUT];
    int tid = threadIdx.x;
    for (int i = tid; i < IN * HID; i += BLK) sw1[i] = w1[i];
    for (int i = tid; i < HID * OUT; i += BLK) sw2[i] = w2[i];
    for (int i = tid; i < OUT; i += BLK) sb[i] = b2[i];
    int row0 = blockIdx.x * BLK;
    for (int i = tid; i < BLK * IN; i += BLK) {
        int r = i / IN, c = i % IN;
        int gr = row0 + r;
        float v = 0.f;
        if (gr < rows) {
            int sr = gidx ? gidx[gr] : gr;
            v = X[(size_t)sr * IN + c];
        }
        sin_[r * (IN + 1) + c] = v;
    }
    __syncthreads();
    {
        float xin[IN];
        #pragma unroll
        for (int i = 0; i < IN; i++) xin[i] = sin_[tid * (IN + 1) + i];
        float hid[HID];
        #pragma unroll
        for (int j4 = 0; j4 < HID / 4; j4++) {
            float a0 = 0, a1 = 0, a2 = 0, a3 = 0;
            #pragma unroll
            for (int i = 0; i < IN; i++) {
                float4 w = *(const float4*)&sw1[i * HID + j4 * 4];
                a0 += xin[i] * w.x; a1 += xin[i] * w.y;
                a2 += xin[i] * w.z; a3 += xin[i] * w.w;
            }
            hid[j4 * 4 + 0] = a0 > 0.f ? a0 : 0.2f * a0;
            hid[j4 * 4 + 1] = a1 > 0.f ? a1 : 0.2f * a1;
            hid[j4 * 4 + 2] = a2 > 0.f ? a2 : 0.2f * a2;
            hid[j4 * 4 + 3] = a3 > 0.f ? a3 : 0.2f * a3;
        }
        #pragma unroll
        for (int o4 = 0; o4 < OUT / 4; o4++) {
            float a0 = sb[o4 * 4 + 0], a1 = sb[o4 * 4 + 1];
            float a2 = sb[o4 * 4 + 2], a3 = sb[o4 * 4 + 3];
            #pragma unroll
            for (int j = 0; j < HID; j++) {
                float4 w = *(const float4*)&sw2[j * OUT + o4 * 4];
                float hj = hid[j];
                a0 += hj * w.x; a1 += hj * w.y; a2 += hj * w.z; a3 += hj * w.w;
            }
            if (FACT) {
                a0 = a0 > 0.f ? a0 : 0.01f * a0;
                a1 = a1 > 0.f ? a1 : 0.01f * a1;
                a2 = a2 > 0.f ? a2 : 0.01f * a2;
                a3 = a3 > 0.f ? a3 : 0.01f * a3;
            }
            sout[tid * OUT + o4 * 4 + 0] = a0;
            sout[tid * OUT + o4 * 4 + 1] = a1;
            sout[tid * OUT + o4 * 4 + 2] = a2;
            sout[tid * OUT + o4 * 4 + 3] = a3;
        }
    }
    __syncthreads();
    int nrows = rows - row0; if (nrows > BLK) nrows = BLK;
    int limit = nrows * OUT;
    for (int i = tid; i < limit; i += BLK) Y[(size_t)row0 * OUT + i] = sout[i];
}

// ---------------- segment softmax over SRC (fp16 logits): online stats, write to DST order ----------------
__global__ void k_softmax1() {
    int g = blockIdx.x * blockDim.x + threadIdx.x;
    int v = g >> 5;
    if (v >= NN) return;
    int lane = g & 31;
    int lo = g_ips[v], hi = g_ips[v + 1];
    float m0 = -1e30f, m1 = -1e30f, s0 = 0.f, s1 = 0.f;
    for (int p = lo; p < hi; p++) {
        float2 w = __half22float2(g_ew1l[(size_t)p * 32 + lane]);
        float n0 = fmaxf(m0, w.x);
        s0 = s0 * __expf(m0 - n0) + __expf(w.x - n0);
        m0 = n0;
        float n1 = fmaxf(m1, w.y);
        s1 = s1 * __expf(m1 - n1) + __expf(w.y - n1);
        m1 = n1;
    }
    float r0 = 1.f / (s0 + 1e-16f), r1 = 1.f / (s1 + 1e-16f);
    for (int p = lo; p < hi; p++) {
        float2 w = __half22float2(g_ew1l[(size_t)p * 32 + lane]);
        float a0 = __expf(w.x - m0) * r0;
        float a1 = __expf(w.y - m1) * r1;
        int pd = g_ps2pd[p];
        g_ew1h[(size_t)pd * 32 + lane] = __floats2half2_rn(a0, a1);
    }
}

__global__ void k_softmax2() {
    int g = blockIdx.x * blockDim.x + threadIdx.x;
    int v = g >> 4;
    if (v >= NN) return;
    int c = g & 15;
    int lo = g_ips[v], hi = g_ips[v + 1];
    float m = -1e30f, s = 0.f;
    for (int p = lo; p < hi; p++) {
        float w = g_ew2[(size_t)p * 16 + c];
        float n = fmaxf(m, w);
        s = s * __expf(m - n) + __expf(w - n);
        m = n;
    }
    float r = 1.f / (s + 1e-16f);
    for (int p = lo; p < hi; p++) {
        float w = g_ew2[(size_t)p * 16 + c];
        int pd = g_ps2pd[p];
        g_ew2d[(size_t)pd * 16 + c] = __expf(w - m) * r;
    }
}

// ---------------- tf32 tensor-core GEMM (kept for K=16 t1) ----------------
#define GNC 512
#define SAS 136

template <int INHALF, int OUTHALF>
__global__ void __launch_bounds__(256) k_gemm_tf32(
    const void* __restrict__ Av, const float* __restrict__ B,
    void* __restrict__ C, int M, int K,
    const float* __restrict__ bias, int act, float slope)
{
    __shared__ __align__(16) uint32_t As[2][16 * SAS];
    __shared__ __align__(16) uint32_t Bs[2][16 * SAS];

    int tid = threadIdx.x;
    int lane = tid & 31, wid = tid >> 5;
    int grp = lane >> 2, tig = lane & 3;
    int wm0 = (wid & 1) * 64, wn0 = (wid >> 1) * 32;
    int brow = blockIdx.y * 128, bcol = blockIdx.x * 128;

    int arow = tid >> 1;
    int akq  = (tid & 1) * 8;

    float acc[4][4][4];
    #pragma unroll
    for (int i = 0; i < 4; i++)
        #pragma unroll
        for (int j = 0; j < 4; j++)
            #pragma unroll
            for (int q = 0; q < 4; q++) acc[i][j][q] = 0.f;

    int KT = K >> 4;
    float4 ra0, ra1, rb0, rb1;

    auto load_tile = [&](int k0) {
        ra0 = make_float4(0.f, 0.f, 0.f, 0.f);
        ra1 = ra0;
        if (brow + arow < M) {
            if (INHALF) {
                const __half* ap = (const __half*)Av + (size_t)(brow + arow) * K + k0 + akq;
                uint4 h8 = *(const uint4*)ap;
                float2 f0 = __half22float2(*(__half2*)&h8.x);
                float2 f1 = __half22float2(*(__half2*)&h8.y);
                float2 f2 = __half22float2(*(__half2*)&h8.z);
                float2 f3 = __half22float2(*(__half2*)&h8.w);
                ra0 = make_float4(f0.x, f0.y, f1.x, f1.y);
                ra1 = make_float4(f2.x, f2.y, f3.x, f3.y);
            } else {
                const float* ap = (const float*)Av + (size_t)(brow + arow) * K + k0 + akq;
                ra0 = *(const float4*)ap;
                ra1 = *(const float4*)(ap + 4);
            }
        }
        int f0 = tid, f1 = tid + 256;
        int r0 = f0 >> 5, n0 = (f0 & 31) * 4;
        int r1 = f1 >> 5, n1 = (f1 & 31) * 4;
        rb0 = *(const float4*)&B[(size_t)(k0 + r0) * GNC + bcol + n0];
        rb1 = *(const float4*)&B[(size_t)(k0 + r1) * GNC + bcol + n1];
    };
    auto store_tile = [&](int buf) {
        As[buf][(akq + 0) * SAS + arow] = f2tf32(ra0.x);
        As[buf][(akq + 1) * SAS + arow] = f2tf32(ra0.y);
        As[buf][(akq + 2) * SAS + arow] = f2tf32(ra0.z);
        As[buf][(akq + 3) * SAS + arow] = f2tf32(ra0.w);
        As[buf][(akq + 4) * SAS + arow] = f2tf32(ra1.x);
        As[buf][(akq + 5) * SAS + arow] = f2tf32(ra1.y);
        As[buf][(akq + 6) * SAS + arow] = f2tf32(ra1.z);
        As[buf][(akq + 7) * SAS + arow] = f2tf32(ra1.w);
        int f0 = tid, f1 = tid + 256;
        int r0 = f0 >> 5, n0 = (f0 & 31) * 4;
        int r1 = f1 >> 5, n1 = (f1 & 31) * 4;
        uint4 b0 = make_uint4(f2tf32(rb0.x), f2tf32(rb0.y), f2tf32(rb0.z), f2tf32(rb0.w));
        uint4 b1 = make_uint4(f2tf32(rb1.x), f2tf32(rb1.y), f2tf32(rb1.z), f2tf32(rb1.w));
        *(uint4*)&Bs[buf][r0 * SAS + n0] = b0;
        *(uint4*)&Bs[buf][r1 * SAS + n1] = b1;
    };

    load_tile(0);
    store_tile(0);
    __syncthreads();

    for (int kt = 0; kt < KT; kt++) {
        bool has_next = (kt + 1 < KT);
        if (has_next) load_tile((kt + 1) << 4);
        int buf = kt & 1;

        #pragma unroll
        for (int ks = 0; ks < 16; ks += 8) {
            uint32_t af[4][4], bf[4][2];
            #pragma unroll
            for (int i = 0; i < 4; i++) {
                int mb = wm0 + i * 16 + grp;
                int kk = ks + tig;
                af[i][0] = As[buf][kk * SAS + mb];
                af[i][1] = As[buf][kk * SAS + mb + 8];
                af[i][2] = As[buf][(kk + 4) * SAS + mb];
                af[i][3] = As[buf][(kk + 4) * SAS + mb + 8];
            }
            #pragma unroll
            for (int j = 0; j < 4; j++) {
                int nb = wn0 + j * 8 + grp;
                int kk = ks + tig;
                bf[j][0] = Bs[buf][kk * SAS + nb];
                bf[j][1] = Bs[buf][(kk + 4) * SAS + nb];
            }
            #pragma unroll
            for (int i = 0; i < 4; i++)
                #pragma unroll
                for (int j = 0; j < 4; j++)
                    mma_tf32(acc[i][j], af[i], bf[j][0], bf[j][1]);
        }
        if (has_next) {
            store_tile((kt + 1) & 1);
            __syncthreads();
        }
    }

    #pragma unroll
    for (int i = 0; i < 4; i++) {
        int r0 = brow + wm0 + i * 16 + grp;
        #pragma unroll
        for (int j = 0; j < 4; j++) {
            int c = bcol + wn0 + j * 8 + tig * 2;
            float b0 = bias ? bias[c] : 0.f;
            float b1 = bias ? bias[c + 1] : 0.f;
            float v0 = acc[i][j][0] + b0, v1 = acc[i][j][1] + b1;
            float v2 = acc[i][j][2] + b0, v3 = acc[i][j][3] + b1;
            if (act) {
                v0 = v0 > 0.f ? v0 : slope * v0;
                v1 = v1 > 0.f ? v1 : slope * v1;
                v2 = v2 > 0.f ? v2 : slope * v2;
                v3 = v3 > 0.f ? v3 : slope * v3;
            }
            if (OUTHALF) {
                __half* Ch = (__half*)C;
                if (r0 < M)     *(__half2*)&Ch[(size_t)r0 * GNC + c]       = __floats2half2_rn(v0, v1);
                if (r0 + 8 < M) *(__half2*)&Ch[(size_t)(r0 + 8) * GNC + c] = __floats2half2_rn(v2, v3);
            } else {
                float* Cf = (float*)C;
                if (r0 < M)     *(float2*)&Cf[(size_t)r0 * GNC + c]       = make_float2(v0, v1);
                if (r0 + 8 < M) *(float2*)&Cf[(size_t)(r0 + 8) * GNC + c] = make_float2(v2, v3);
            }
        }
    }
}

// ---------------- fp16 m16n8k16 GEMM: C[M,512] = act(A[M,K]@B[K,512]+bias), K%32==0 ----------------
#define FSA 20

template <int AHALF, int OUTHALF>
__global__ void __launch_bounds__(256) k_gemm_f16(
    const void* __restrict__ Av, const float* __restrict__ B,
    void* __restrict__ C, int M, int K,
    const float* __restrict__ bias, int act, float slope)
{
    __shared__ __align__(16) uint32_t As[2][128 * FSA];
    __shared__ __align__(16) uint32_t Bs[2][128 * FSA];

    int tid = threadIdx.x;
    int lane = tid & 31, wid = tid >> 5;
    int grp = lane >> 2, tig = lane & 3;
    int wm0 = (wid & 1) * 64, wn0 = (wid >> 1) * 32;
    int brow = blockIdx.y * 128, bcol = blockIdx.x * 128;

    int am = tid >> 1, aq = tid & 1;

    float acc[4][4][4];
    #pragma unroll
    for (int i = 0; i < 4; i++)
        #pragma unroll
        for (int j = 0; j < 4; j++)
            #pragma unroll
            for (int q = 0; q < 4; q++) acc[i][j][q] = 0.f;

    int KT = K >> 5;
    uint32_t ua[8];
    float rb0[8], rb1[8];

    auto load_tile = [&](int k0) {
        if (brow + am < M) {
            if (AHALF) {
                const __half* ap = (const __half*)Av + (size_t)(brow + am) * K + k0 + 16 * aq;
                uint4 u0 = *(const uint4*)ap;
                uint4 u1 = *(const uint4*)(ap + 8);
                ua[0] = u0.x; ua[1] = u0.y; ua[2] = u0.z; ua[3] = u0.w;
                ua[4] = u1.x; ua[5] = u1.y; ua[6] = u1.z; ua[7] = u1.w;
            } else {
                const float* ap = (const float*)Av + (size_t)(brow + am) * K + k0 + 16 * aq;
                #pragma unroll
                for (int j = 0; j < 4; j++) {
                    float4 f = *(const float4*)(ap + 4 * j);
                    __half2 h0 = __floats2half2_rn(f.x, f.y);
                    __half2 h1 = __floats2half2_rn(f.z, f.w);
                    ua[2 * j]     = *(uint32_t*)&h0;
                    ua[2 * j + 1] = *(uint32_t*)&h1;
                }
            }
        } else {
            #pragma unroll
            for (int j = 0; j < 8; j++) ua[j] = 0u;
        }
        #pragma unroll
        for (int i = 0; i < 8; i++) {
            int idx = tid + 256 * i;
            int n = idx & 127, kh = idx >> 7;
            const float* bp = B + (size_t)(k0 + 2 * kh) * GNC + bcol + n;
            rb0[i] = bp[0];
            rb1[i] = bp[GNC];
        }
    };
    auto store_tile = [&](int buf) {
        #pragma unroll
        for (int j = 0; j < 8; j++) As[buf][am * FSA + 8 * aq + j] = ua[j];
        #pragma unroll
        for (int i = 0; i < 8; i++) {
            int idx = tid + 256 * i;
            int n = idx & 127, kh = idx >> 7;
            __half2 h = __floats2half2_rn(rb0[i], rb1[i]);
            Bs[buf][n * FSA + kh] = *(uint32_t*)&h;
        }
    };

    load_tile(0);
    store_tile(0);
    __syncthreads();

    for (int kt = 0; kt < KT; kt++) {
        bool has_next = (kt + 1 < KT);
        if (has_next) load_tile((kt + 1) << 5);
        int buf = kt & 1;

        #pragma unroll
        for (int ks = 0; ks < 2; ks++) {
            uint32_t af[4][4], bf[4][2];
            #pragma unroll
            for (int i = 0; i < 4; i++) {
                int m = wm0 + i * 16 + grp;
                int b0 = m * FSA + ks * 8;
                int b1 = (m + 8) * FSA + ks * 8;
                af[i][0] = As[buf][b0 + tig];
                af[i][1] = As[buf][b1 + tig];
                af[i][2] = As[buf][b0 + tig + 4];
                af[i][3] = As[buf][b1 + tig + 4];
            }
            #pragma unroll
            for (int j = 0; j < 4; j++) {
                int n = wn0 + j * 8 + grp;
                bf[j][0] = Bs[buf][n * FSA + ks * 8 + tig];
                bf[j][1] = Bs[buf][n * FSA + ks * 8 + tig + 4];
            }
            #pragma unroll
            for (int i = 0; i < 4; i++)
                #pragma unroll
                for (int j = 0; j < 4; j++)
                    mma_f16(acc[i][j], af[i], bf[j][0], bf[j][1]);
        }
        if (has_next) {
            store_tile((kt + 1) & 1);
            __syncthreads();
        }
    }

    #pragma unroll
    for (int i = 0; i < 4; i++) {
        int r0 = brow + wm0 + i * 16 + grp;
        #pragma unroll
        for (int j = 0; j < 4; j++) {
            int c = bcol + wn0 + j * 8 + tig * 2;
            float b0 = bias ? bias[c] : 0.f;
            float b1 = bias ? bias[c + 1] : 0.f;
            float v0 = acc[i][j][0] + b0, v1 = acc[i][j][1] + b1;
            float v2 = acc[i][j][2] + b0, v3 = acc[i][j][3] + b1;
            if (act) {
                v0 = v0 > 0.f ? v0 : slope * v0;
                v1 = v1 > 0.f ? v1 : slope * v1;
                v2 = v2 > 0.f ? v2 : slope * v2;
                v3 = v3 > 0.f ? v3 : slope * v3;
            }
            if (OUTHALF) {
                __half* Ch = (__half*)C;
                if (r0 < M)     *(__half2*)&Ch[(size_t)r0 * GNC + c]       = __floats2half2_rn(v0, v1);
                if (r0 + 8 < M) *(__half2*)&Ch[(size_t)(r0 + 8) * GNC + c] = __floats2half2_rn(v2, v3);
            } else {
                float* Cf = (float*)C;
                if (r0 < M)     *(float2*)&Cf[(size_t)r0 * GNC + c]       = make_float2(v0, v1);
                if (r0 + 8 < M) *(float2*)&Cf[(size_t)(r0 + 8) * GNC + c] = make_float2(v2, v3);
            }
        }
    }
}

// ---------------- layer-1 aggregation (unroll-2): streaming attention, gathered xh1h ----------------
__global__ void __launch_bounds__(256) k_agg1(
    const float* __restrict__ bias, const float* __restrict__ alphap)
{
    int g = blockIdx.x * blockDim.x + threadIdx.x;
    int v = g >> 5;
    if (v >= NN) return;
    int lane = g & 31;
    float2 acc[8];
    #pragma unroll
    for (int k = 0; k < 8; k++) acc[k] = make_float2(0.f, 0.f);
    int lo = g_ipd[v], hi = g_ipd[v + 1];
    int p = lo;
    for (; p + 1 < hi; p += 2) {
        int s0 = g_src_of_pd[p];
        int s1 = g_src_of_pd[p + 1];
        float2 a0 = __half22float2(g_ew1h[(size_t)p * 32 + lane]);
        float2 a1 = __half22float2(g_ew1h[(size_t)(p + 1) * 32 + lane]);
        const __half2* x0 = g_xh1h + (size_t)s0 * 256;
        const __half2* x1 = g_xh1h + (size_t)s1 * 256;
        #pragma unroll
        for (int k = 0; k < 8; k++) {
            float2 f0 = __half22float2(x0[lane + 32 * k]);
            float2 f1 = __half22float2(x1[lane + 32 * k]);
            acc[k].x += a0.x * f0.x + a1.x * f1.x;
            acc[k].y += a0.y * f0.y + a1.y * f1.y;
        }
    }
    if (p < hi) {
        int s0 = g_src_of_pd[p];
        float2 a0 = __half22float2(g_ew1h[(size_t)p * 32 + lane]);
        const __half2* x0 = g_xh1h + (size_t)s0 * 256;
        #pragma unroll
        for (int k = 0; k < 8; k++) {
            float2 f0 = __half22float2(x0[lane + 32 * k]);
            acc[k].x += a0.x * f0.x;
            acc[k].y += a0.y * f0.y;
        }
    }

    float al = *alphap;
    const __half2* pr = g_p1h + (size_t)v * 256;
    __half2* hw = g_hh + (size_t)v * 256;
    #pragma unroll
    for (int k = 0; k < 8; k++) {
        int j = 2 * lane + 64 * k;
        float2 pv = __half22float2(pr[lane + 32 * k]);
        float o0 = fmaxf(acc[k].x + bias[j]     + al * pv.x, 0.f);
        float o1 = fmaxf(acc[k].y + bias[j + 1] + al * pv.y, 0.f);
        hw[lane + 32 * k] = __floats2half2_rn(o0, o1);
    }
}

// ---------------- xh2 = h @ W_src2  ([N,512]x[512,16], h fp16) ----------------
__global__ void __launch_bounds__(256) k_xh2(const float* __restrict__ W) {
    __shared__ float sW[512 * 16];
    int tid = threadIdx.x;
    for (int i = tid; i < 512 * 16; i += 256) sW[i] = W[i];
    __syncthreads();
    int g = blockIdx.x * 256 + tid;
    int v = g >> 4, c = g & 15;
    if (v >= NN) return;
    const __half2* hr = g_hh + (size_t)v * 256;
    float acc = 0.f;
    #pragma unroll 4
    for (int i = 0; i < 256; i++) {
        float2 f = __half22float2(hr[i]);
        int j = 2 * (i & 31) + 64 * (i >> 5);
        acc += f.x * sW[j * 16 + c] + f.y * sW[(j + 1) * 16 + c];
    }
    g_xh2[g] = acc;
}

// ---------------- layer-2 aggregation + bias + alpha*p2 + log_softmax ----------------
__global__ void __launch_bounds__(256) k_agg2(
    const float* __restrict__ bias2, const float* __restrict__ alphap,
    float* __restrict__ out)
{
    int g = blockIdx.x * 256 + threadIdx.x;
    int v = g >> 4, c = g & 15;
    float acc = 0.f;
    int lo = g_ipd[v], hi = g_ipd[v + 1];
    for (int p = lo; p < hi; p++) {
        int s = g_src_of_pd[p];
        acc += g_ew2d[(size_t)p * 16 + c] * g_xh2[s * 16 + c];
    }
    float o = acc + bias2[c] + (*alphap) * g_p2[g];
    float m = o;
    #pragma unroll
    for (int d = 8; d > 0; d >>= 1) m = fmaxf(m, __shfl_xor_sync(0xffffffffu, m, d, 16));
    float se = __expf(o - m);
    #pragma unroll
    for (int d = 8; d > 0; d >>= 1) se += __shfl_xor_sync(0xffffffffu, se, d, 16);
    out[g] = o - m - logf(se);
}

// ---------------- stream/event context ----------------
struct HxCtx {
    cudaStream_t sB, sC;
    cudaEvent_t ev0, evCSR, evB, evC;
    HxCtx() {
        cudaStreamCreateWithFlags(&sB, cudaStreamNonBlocking);
        cudaStreamCreateWithFlags(&sC, cudaStreamNonBlocking);
        cudaEventCreateWithFlags(&ev0,   cudaEventDisableTiming);
        cudaEventCreateWithFlags(&evCSR, cudaEventDisableTiming);
        cudaEventCreateWithFlags(&evB,   cudaEventDisableTiming);
        cudaEventCreateWithFlags(&evC,   cudaEventDisableTiming);
        cudaFuncSetAttribute(k_emlp1, cudaFuncAttributeMaxDynamicSharedMemorySize, EMLP_SMEM);
    }
};
static HxCtx g_ctx;

// ---------------- host launch ----------------
extern "C" void kernel_launch(void* const* d_in, const int* in_sizes, int n_in,
                              void* d_out, int out_size)
{
    const float* x       = (const float*)d_in[0];
    const int*   ei      = (const int*)  d_in[1];
    const float* alpha   = (const float*)d_in[2];
    const float* k_ricci = (const float*)d_in[3];
    const float* e_poinc = (const float*)d_in[4];
    const float* W1      = (const float*)d_in[5];
    const float* h1w1    = (const float*)d_in[6];
    const float* h1w2    = (const float*)d_in[7];
    const float* h1b2    = (const float*)d_in[8];
    const float* p1w1    = (const float*)d_in[9];
    const float* p1w2    = (const float*)d_in[10];
    const float* p1b2    = (const float*)d_in[11];
    const float* bias1   = (const float*)d_in[12];
    const float* W2      = (const float*)d_in[13];
    const float* h2w1    = (const float*)d_in[14];
    const float* h2w2    = (const float*)d_in[15];
    const float* h2b2    = (const float*)d_in[16];
    const float* p2w1    = (const float*)d_in[17];
    const float* p2w2    = (const float*)d_in[18];
    const float* p2b2    = (const float*)d_in[19];
    const float* bias2   = (const float*)d_in[20];
    float* out = (float*)d_out;

    void *p_xh1h, *p_t1h, *p_p1h, *p_ew1l;
    float *p_ew2, *p_p2;
    int *p_eid_src;
    cudaGetSymbolAddress(&p_xh1h, g_xh1h);
    cudaGetSymbolAddress(&p_t1h,  g_t1h);
    cudaGetSymbolAddress(&p_p1h,  g_p1h);
    cudaGetSymbolAddress(&p_ew1l, g_ew1l);
    cudaGetSymbolAddress((void**)&p_ew2, g_ew2);
    cudaGetSymbolAddress((void**)&p_p2,  g_p2);
    cudaGetSymbolAddress((void**)&p_eid_src, g_eid_src);

    cudaStream_t sB = g_ctx.sB, sC = g_ctx.sC;

    // fork
    cudaEventRecord(g_ctx.ev0, 0);
    cudaStreamWaitEvent(sB, g_ctx.ev0, 0);
    cudaStreamWaitEvent(sC, g_ctx.ev0, 0);

    // ---- stream B: CSR + layer-1 attention (the agg1 prerequisites ONLY) ----
    k_zero<<<(NN + 255) / 256, 256, 0, sB>>>();
    k_count<<<(ET + 255) / 256, 256, 0, sB>>>(ei);
    k_scan<<<2, 1024, 0, sB>>>();
    k_fill<<<(ET + 255) / 256, 256, 0, sB>>>(ei);
    cudaEventRecord(g_ctx.evCSR, sB);
    k_emlp1<<<(ET + 127) / 128, 256, EMLP_SMEM, sB>>>(k_ricci, h1w1, h1w2, h1b2, (__half2*)p_ew1l);
    k_softmax1<<<(NN * 32) / 256, 256, 0, sB>>>();
    cudaEventRecord(g_ctx.evB, sB);

    // ---- stream C: layer-2 attention + p2 (only needed by agg2; overlaps with agg1/xh2) ----
    cudaStreamWaitEvent(sC, g_ctx.evCSR, 0);
    k_mlp<16, 16, 16, 128, false><<<(ET + 127) / 128, 128, 0, sC>>>(k_ricci, h2w1, h2w2, h2b2, p_ew2, ET, p_eid_src);
    k_softmax2<<<(NN * 16) / 256, 256, 0, sC>>>();
    k_mlp<16, 16, 16, 128, true><<<(NN + 127) / 128, 128, 0, sC>>>(e_poinc, p2w1, p2w2, p2b2, p_p2, NN, nullptr);
    cudaEventRecord(g_ctx.evC, sC);

    // ---- default stream: dense chain (fp16 HMMA for the two big GEMMs) ----
    dim3 gg(512 / 128, (NN + 127) / 128);
    k_gemm_f16 <0, 1><<<gg, 256>>>(x,       W1,   p_xh1h, NN, 128, nullptr, 0, 0.f);
    k_gemm_tf32<0, 1><<<gg, 256>>>(e_poinc, p1w1, p_t1h,  NN, 16,  nullptr, 1, 0.2f);
    k_gemm_f16 <1, 1><<<gg, 256>>>(p_t1h,   p1w2, p_p1h,  NN, 512, p1b2,    1, 0.01f);

    // join for agg1 (needs softmax1 + xh1 + p1)
    cudaStreamWaitEvent(0, g_ctx.evB, 0);
    k_agg1<<<(NN * 32) / 256, 256>>>(bias1, alpha);
    k_xh2<<<(NN * 16) / 256, 256>>>(W2);

    // join for agg2 (needs xh2 + ew2d + p2)
    cudaStreamWaitEvent(0, g_ctx.evC, 0);
    k_agg2<<<(NN * 16) / 256, 256>>>(bias2, alpha, out);
}

// round 13
// speedup vs baseline: 1.0964x; 1.0199x over previous
#include <cuda_runtime.h>
#include <cuda_fp16.h>
#include <math.h>
#include <stdint.h>

#define NN 50000
#define EE 600000
#define ET 650000   // EE + NN (self loops appended)

// ---------------- scratch (static device memory; allocation-free) ----------------
__device__ __half2 g_xh1h[(size_t)NN * 256];   // xh1 as half2 (512 ch)
__device__ __half  g_t1h [(size_t)NN * 512];   // t1 as half
__device__ __half2 g_p1h [(size_t)NN * 256];   // p1 as half2
__device__ __half2 g_hh  [(size_t)NN * 256];   // h as half2
__device__ __half2 g_ew1l[(size_t)ET * 32];    // logits, src-position order, fp16 (half2 h = ch 2h,2h+1)
__device__ __half2 g_ew1h[(size_t)ET * 32];    // normalized attention, DST-position order, fp16
__device__ __half  g_ew2h[(size_t)ET * 16];    // logits layer2, src-position order, fp16
__device__ __half  g_ew2d[(size_t)ET * 16];    // normalized attention layer2, DST-position order, fp16
__device__ float   g_xh2[NN * 16];
__device__ float   g_p2 [NN * 16];

__device__ int g_cnt_src[NN], g_cnt_dst[NN];
__device__ int g_ips[NN + 1], g_ipd[NN + 1];
__device__ int g_cur_src[NN], g_cur_dst[NN];
__device__ int g_eid_src[ET];
__device__ int g_ps2pd[ET];                    // src-CSR position -> dst-CSR position
__device__ int g_src_of_pd[ET];                // dst-CSR position -> src node

// ---------------- CSR build ----------------
__global__ void k_zero() {
    int i = blockIdx.x * blockDim.x + threadIdx.x;
    if (i < NN) { g_cnt_src[i] = 0; g_cnt_dst[i] = 0; }
}

__global__ void k_count(const int* __restrict__ ei) {
    int e = blockIdx.x * blockDim.x + threadIdx.x;
    if (e >= ET) return;
    int s = (e < EE) ? ei[e]      : e - EE;
    int d = (e < EE) ? ei[EE + e] : e - EE;
    atomicAdd(&g_cnt_src[s], 1);
    atomicAdd(&g_cnt_dst[d], 1);
}

__global__ void k_scan() {
    const int* cnt = (blockIdx.x == 0) ? g_cnt_src : g_cnt_dst;
    int* ip  = (blockIdx.x == 0) ? g_ips : g_ipd;
    int* cur = (blockIdx.x == 0) ? g_cur_src : g_cur_dst;
    __shared__ int wsum[32];
    int tid = threadIdx.x, lane = tid & 31, wid = tid >> 5;
    int carry = 0;
    for (int base = 0; base < NN; base += 1024) {
        int i = base + tid;
        int v = (i < NN) ? cnt[i] : 0;
        int x = v;
        #pragma unroll
        for (int o = 1; o < 32; o <<= 1) {
            int t = __shfl_up_sync(0xffffffffu, x, o);
            if (lane >= o) x += t;
        }
        if (lane == 31) wsum[wid] = x;
        __syncthreads();
        if (wid == 0) {
            int y = wsum[lane];
            #pragma unroll
            for (int o = 1; o < 32; o <<= 1) {
                int t = __shfl_up_sync(0xffffffffu, y, o);
                if (lane >= o) y += t;
            }
            wsum[lane] = y;
        }
        __syncthreads();
        int woff = (wid == 0) ? 0 : wsum[wid - 1];
        int excl = x + woff - v;
        if (i < NN) { ip[i] = carry + excl; cur[i] = carry + excl; }
        int total = wsum[31];
        __syncthreads();
        carry += total;
    }
    if (tid == 0) ip[NN] = carry;
}

__global__ void k_fill(const int* __restrict__ ei) {
    int e = blockIdx.x * blockDim.x + threadIdx.x;
    if (e >= ET) return;
    int s = (e < EE) ? ei[e]      : e - EE;
    int d = (e < EE) ? ei[EE + e] : e - EE;
    int ps = atomicAdd(&g_cur_src[s], 1);
    int pd = atomicAdd(&g_cur_dst[d], 1);
    g_eid_src[ps] = e;
    g_ps2pd[ps] = pd;
    g_src_of_pd[pd] = s;
}

// ---------------- mma helpers ----------------
__device__ __forceinline__ uint32_t f2tf32(float f) {
    uint32_t u;
    asm("cvt.rna.tf32.f32 %0, %1;" : "=r"(u) : "f"(f));
    return u;
}

__device__ __forceinline__ void mma_tf32(float* c, const uint32_t* a, uint32_t b0, uint32_t b1) {
    asm volatile(
        "mma.sync.aligned.m16n8k8.row.col.f32.tf32.tf32.f32 "
        "{%0,%1,%2,%3}, {%4,%5,%6,%7}, {%8,%9}, {%0,%1,%2,%3};"
        : "+f"(c[0]), "+f"(c[1]), "+f"(c[2]), "+f"(c[3])
        : "r"(a[0]), "r"(a[1]), "r"(a[2]), "r"(a[3]), "r"(b0), "r"(b1));
}

__device__ __forceinline__ void mma_f16(float* c, const uint32_t* a, uint32_t b0, uint32_t b1) {
    asm volatile(
        "mma.sync.aligned.m16n8k16.row.col.f32.f16.f16.f32 "
        "{%0,%1,%2,%3}, {%4,%5,%6,%7}, {%8,%9}, {%0,%1,%2,%3};"
        : "+f"(c[0]), "+f"(c[1]), "+f"(c[2]), "+f"(c[3])
        : "r"(a[0]), "r"(a[1]), "r"(a[2]), "r"(a[3]), "r"(b0), "r"(b1));
}

// ---------------- edge MLP layer1 on tensor cores (gather-staged, fp16 logits out) ----------------
#define ES1 136
#define EH  68
#define EB  72
#define EMLP_SMEM ((128*EH + 16*EB + 64*EB + 64 + 128) * 4)

__global__ void __launch_bounds__(256) k_emlp1(
    const float* __restrict__ KR, const float* __restrict__ w1,
    const float* __restrict__ w2, const float* __restrict__ b2,
    __half2* __restrict__ EW)
{
    extern __shared__ uint32_t dyn[];
    uint32_t* Hs  = dyn;
    uint32_t* As1 = dyn;
    uint32_t* Bs1 = dyn + 128 * EH;
    uint32_t* Bs2 = Bs1 + 16 * EB;
    float*    sb2 = (float*)(Bs2 + 64 * EB);
    int*      se  = (int*)(sb2 + 64);

    int tid = threadIdx.x, lane = tid & 31, wid = tid >> 5;
    int grp = lane >> 2, tig = lane & 3;
    int row0 = blockIdx.x * 128;
    int m0 = wid * 16;

    for (int i = tid; i < 16 * 64; i += 256) { int k = i >> 6, n = i & 63; Bs1[k * EB + n] = f2tf32(w1[i]); }
    for (int i = tid; i < 64 * 64; i += 256) { int k = i >> 6, n = i & 63; Bs2[k * EB + n] = f2tf32(w2[i]); }
    if (tid < 64) sb2[tid] = b2[tid];
    if (tid < 128) se[tid] = (row0 + tid < ET) ? g_eid_src[row0 + tid] : -1;
    __syncthreads();

    {
        int r = tid >> 1, q = (tid & 1) * 8;
        int e = se[r];
        float4 v0 = make_float4(0.f, 0.f, 0.f, 0.f), v1 = v0;
        if (e >= 0) {
            const float* p = KR + (size_t)e * 16 + q;
            v0 = *(const float4*)p;
            v1 = *(const float4*)(p + 4);
        }
        As1[(q + 0) * ES1 + r] = f2tf32(v0.x);
        As1[(q + 1) * ES1 + r] = f2tf32(v0.y);
        As1[(q + 2) * ES1 + r] = f2tf32(v0.z);
        As1[(q + 3) * ES1 + r] = f2tf32(v0.w);
        As1[(q + 4) * ES1 + r] = f2tf32(v1.x);
        As1[(q + 5) * ES1 + r] = f2tf32(v1.y);
        As1[(q + 6) * ES1 + r] = f2tf32(v1.z);
        As1[(q + 7) * ES1 + r] = f2tf32(v1.w);
    }
    __syncthreads();

    float acc1[8][4];
    #pragma unroll
    for (int j = 0; j < 8; j++)
        #pragma unroll
        for (int q = 0; q < 4; q++) acc1[j][q] = 0.f;
    #pragma unroll
    for (int kk = 0; kk < 16; kk += 8) {
        uint32_t a[4];
        a[0] = As1[(kk + tig) * ES1 + m0 + grp];
        a[1] = As1[(kk + tig) * ES1 + m0 + grp + 8];
        a[2] = As1[(kk + tig + 4) * ES1 + m0 + grp];
        a[3] = As1[(kk + tig + 4) * ES1 + m0 + grp + 8];
        #pragma unroll
        for (int j = 0; j < 8; j++) {
            uint32_t b0 = Bs1[(kk + tig) * EB + j * 8 + grp];
            uint32_t b1 = Bs1[(kk + tig + 4) * EB + j * 8 + grp];
            mma_tf32(acc1[j], a, b0, b1);
        }
    }
    __syncthreads();

    #pragma unroll
    for (int j = 0; j < 8; j++) {
        float c0 = acc1[j][0], c1 = acc1[j][1], c2 = acc1[j][2], c3 = acc1[j][3];
        c0 = c0 > 0.f ? c0 : 0.2f * c0;
        c1 = c1 > 0.f ? c1 : 0.2f * c1;
        c2 = c2 > 0.f ? c2 : 0.2f * c2;
        c3 = c3 > 0.f ? c3 : 0.2f * c3;
        uint2 u0 = make_uint2(f2tf32(c0), f2tf32(c1));
        uint2 u1 = make_uint2(f2tf32(c2), f2tf32(c3));
        *(uint2*)&Hs[(m0 + grp) * EH + j * 8 + 2 * tig]     = u0;
        *(uint2*)&Hs[(m0 + grp + 8) * EH + j * 8 + 2 * tig] = u1;
    }
    __syncthreads();

    float acc2[8][4];
    #pragma unroll
    for (int j = 0; j < 8; j++)
        #pragma unroll
        for (int q = 0; q < 4; q++) acc2[j][q] = 0.f;
    #pragma unroll
    for (int kk = 0; kk < 64; kk += 8) {
        uint32_t a[4];
        a[0] = Hs[(m0 + grp) * EH + kk + tig];
        a[1] = Hs[(m0 + grp + 8) * EH + kk + tig];
        a[2] = Hs[(m0 + grp) * EH + kk + tig + 4];
        a[3] = Hs[(m0 + grp + 8) * EH + kk + tig + 4];
        #pragma unroll
        for (int j = 0; j < 8; j++) {
            uint32_t b0 = Bs2[(kk + tig) * EB + j * 8 + grp];
            uint32_t b1 = Bs2[(kk + tig + 4) * EB + j * 8 + grp];
            mma_tf32(acc2[j], a, b0, b1);
        }
    }

    // fp16 logits out: half2 index h = channels (2h, 2h+1); c = j*8+2*tig -> h = j*4+tig
    int r0 = row0 + m0 + grp, r1 = r0 + 8;
    #pragma unroll
    for (int j = 0; j < 8; j++) {
        int c = j * 8 + 2 * tig;
        float b0 = sb2[c], b1 = sb2[c + 1];
        int h = j * 4 + tig;
        if (r0 < ET) EW[(size_t)r0 * 32 + h] = __floats2half2_rn(acc2[j][0] + b0, acc2[j][1] + b1);
        if (r1 < ET) EW[(size_t)r1 * 32 + h] = __floats2half2_rn(acc2[j][2] + b0, acc2[j][3] + b1);
    }
}

// ---------------- fused small MLP (SIMT), optional gather-in / half-out ----------------
template <int IN, int HID, int OUT, int BLK, bool FACT, bool OUTHALF>
__global__ void __launch_bounds__(BLK) k_mlp(
    const float* __restrict__ X, const float* __restrict__ w1,
    const float* __restrict__ w2, const float* __restrict__ b2,
    void* __restrict__ Yv, int rows, const int* __restrict__ gidx)
{
    __shared__ __align__(16) float sw1[IN * HID];
    __shared__ __align__(16) float sw2[HID * OUT];
    __shared__ __align__(16) float sb[OUT];
    __shared__ float sin_[BLK * (IN + 1)];
    __shared__ float sout[BLK * OUT];
    int tid = threadIdx.x;
    for (int i = tid; i < IN * HID; i += BLK) sw1[i] = w1[i];
    for (int i = tid; i < HID * OUT; i += BLK) sw2[i] = w2[i];
    for (int i = tid; i < OUT; i += BLK) sb[i] = b2[i];
    int row0 = blockIdx.x * BLK;
    for (int i = tid; i < BLK * IN; i += BLK) {
        int r = i / IN, c = i % IN;
        int gr = row0 + r;
        float v = 0.f;
        if (gr < rows) {
            int sr = gidx ? gidx[gr] : gr;
            v = X[(size_t)sr * IN + c];
        }
        sin_[r * (IN + 1) + c] = v;
    }
    __syncthreads();
    {
        float xin[IN];
        #pragma unroll
        for (int i = 0; i < IN; i++) xin[i] = sin_[tid * (IN + 1) + i];
        float hid[HID];
        #pragma unroll
        for (int j4 = 0; j4 < HID / 4; j4++) {
            float a0 = 0, a1 = 0, a2 = 0, a3 = 0;
            #pragma unroll
            for (int i = 0; i < IN; i++) {
                float4 w = *(const float4*)&sw1[i * HID + j4 * 4];
                a0 += xin[i] * w.x; a1 += xin[i] * w.y;
                a2 += xin[i] * w.z; a3 += xin[i] * w.w;
            }
            hid[j4 * 4 + 0] = a0 > 0.f ? a0 : 0.2f * a0;
            hid[j4 * 4 + 1] = a1 > 0.f ? a1 : 0.2f * a1;
            hid[j4 * 4 + 2] = a2 > 0.f ? a2 : 0.2f * a2;
            hid[j4 * 4 + 3] = a3 > 0.f ? a3 : 0.2f * a3;
        }
        #pragma unroll
        for (int o4 = 0; o4 < OUT / 4; o4++) {
            float a0 = sb[o4 * 4 + 0], a1 = sb[o4 * 4 + 1];
            float a2 = sb[o4 * 4 + 2], a3 = sb[o4 * 4 + 3];
            #pragma unroll
            for (int j = 0; j < HID; j++) {
                float4 w = *(const float4*)&sw2[j * OUT + o4 * 4];
                float hj = hid[j];
                a0 += hj * w.x; a1 += hj * w.y; a2 += hj * w.z; a3 += hj * w.w;
            }
            if (FACT) {
                a0 = a0 > 0.f ? a0 : 0.01f * a0;
                a1 = a1 > 0.f ? a1 : 0.01f * a1;
                a2 = a2 > 0.f ? a2 : 0.01f * a2;
                a3 = a3 > 0.f ? a3 : 0.01f * a3;
            }
            sout[tid * OUT + o4 * 4 + 0] = a0;
            sout[tid * OUT + o4 * 4 + 1] = a1;
            sout[tid * OUT + o4 * 4 + 2] = a2;
            sout[tid * OUT + o4 * 4 + 3] = a3;
        }
    }
    __syncthreads();
    int nrows = rows - row0; if (nrows > BLK) nrows = BLK;
    int limit = nrows * OUT;
    if (OUTHALF) {
        __half* Y = (__half*)Yv;
        for (int i = tid; i < limit; i += BLK) Y[(size_t)row0 * OUT + i] = __float2half_rn(sout[i]);
    } else {
        float* Y = (float*)Yv;
        for (int i = tid; i < limit; i += BLK) Y[(size_t)row0 * OUT + i] = sout[i];
    }
}

// ---------------- segment softmax over SRC (fp16 logits): online stats, write to DST order ----------------
__global__ void k_softmax1() {
    int g = blockIdx.x * blockDim.x + threadIdx.x;
    int v = g >> 5;
    if (v >= NN) return;
    int lane = g & 31;
    int lo = g_ips[v], hi = g_ips[v + 1];
    float m0 = -1e30f, m1 = -1e30f, s0 = 0.f, s1 = 0.f;
    for (int p = lo; p < hi; p++) {
        float2 w = __half22float2(g_ew1l[(size_t)p * 32 + lane]);
        float n0 = fmaxf(m0, w.x);
        s0 = s0 * __expf(m0 - n0) + __expf(w.x - n0);
        m0 = n0;
        float n1 = fmaxf(m1, w.y);
        s1 = s1 * __expf(m1 - n1) + __expf(w.y - n1);
        m1 = n1;
    }
    float r0 = 1.f / (s0 + 1e-16f), r1 = 1.f / (s1 + 1e-16f);
    for (int p = lo; p < hi; p++) {
        float2 w = __half22float2(g_ew1l[(size_t)p * 32 + lane]);
        float a0 = __expf(w.x - m0) * r0;
        float a1 = __expf(w.y - m1) * r1;
        int pd = g_ps2pd[p];
        g_ew1h[(size_t)pd * 32 + lane] = __floats2half2_rn(a0, a1);
    }
}

__global__ void k_softmax2() {
    int g = blockIdx.x * blockDim.x + threadIdx.x;
    int v = g >> 4;
    if (v >= NN) return;
    int c = g & 15;
    int lo = g_ips[v], hi = g_ips[v + 1];
    float m = -1e30f, s = 0.f;
    for (int p = lo; p < hi; p++) {
        float w = __half2float(g_ew2h[(size_t)p * 16 + c]);
        float n = fmaxf(m, w);
        s = s * __expf(m - n) + __expf(w - n);
        m = n;
    }
    float r = 1.f / (s + 1e-16f);
    for (int p = lo; p < hi; p++) {
        float w = __half2float(g_ew2h[(size_t)p * 16 + c]);
        int pd = g_ps2pd[p];
        g_ew2d[(size_t)pd * 16 + c] = __float2half_rn(__expf(w - m) * r);
    }
}

// ---------------- tf32 tensor-core GEMM (kept for K=16 t1) ----------------
#define GNC 512
#define SAS 136

template <int INHALF, int OUTHALF>
__global__ void __launch_bounds__(256) k_gemm_tf32(
    const void* __restrict__ Av, const float* __restrict__ B,
    void* __restrict__ C, int M, int K,
    const float* __restrict__ bias, int act, float slope)
{
    __shared__ __align__(16) uint32_t As[2][16 * SAS];
    __shared__ __align__(16) uint32_t Bs[2][16 * SAS];

    int tid = threadIdx.x;
    int lane = tid & 31, wid = tid >> 5;
    int grp = lane >> 2, tig = lane & 3;
    int wm0 = (wid & 1) * 64, wn0 = (wid >> 1) * 32;
    int brow = blockIdx.y * 128, bcol = blockIdx.x * 128;

    int arow = tid >> 1;
    int akq  = (tid & 1) * 8;

    float acc[4][4][4];
    #pragma unroll
    for (int i = 0; i < 4; i++)
        #pragma unroll
        for (int j = 0; j < 4; j++)
            #pragma unroll
            for (int q = 0; q < 4; q++) acc[i][j][q] = 0.f;

    int KT = K >> 4;
    float4 ra0, ra1, rb0, rb1;

    auto load_tile = [&](int k0) {
        ra0 = make_float4(0.f, 0.f, 0.f, 0.f);
        ra1 = ra0;
        if (brow + arow < M) {
            if (INHALF) {
                const __half* ap = (const __half*)Av + (size_t)(brow + arow) * K + k0 + akq;
                uint4 h8 = *(const uint4*)ap;
                float2 f0 = __half22float2(*(__half2*)&h8.x);
                float2 f1 = __half22float2(*(__half2*)&h8.y);
                float2 f2 = __half22float2(*(__half2*)&h8.z);
                float2 f3 = __half22float2(*(__half2*)&h8.w);
                ra0 = make_float4(f0.x, f0.y, f1.x, f1.y);
                ra1 = make_float4(f2.x, f2.y, f3.x, f3.y);
            } else {
                const float* ap = (const float*)Av + (size_t)(brow + arow) * K + k0 + akq;
                ra0 = *(const float4*)ap;
                ra1 = *(const float4*)(ap + 4);
            }
        }
        int f0 = tid, f1 = tid + 256;
        int r0 = f0 >> 5, n0 = (f0 & 31) * 4;
        int r1 = f1 >> 5, n1 = (f1 & 31) * 4;
        rb0 = *(const float4*)&B[(size_t)(k0 + r0) * GNC + bcol + n0];
        rb1 = *(const float4*)&B[(size_t)(k0 + r1) * GNC + bcol + n1];
    };
    auto store_tile = [&](int buf) {
        As[buf][(akq + 0) * SAS + arow] = f2tf32(ra0.x);
        As[buf][(akq + 1) * SAS + arow] = f2tf32(ra0.y);
        As[buf][(akq + 2) * SAS + arow] = f2tf32(ra0.z);
        As[buf][(akq + 3) * SAS + arow] = f2tf32(ra0.w);
        As[buf][(akq + 4) * SAS + arow] = f2tf32(ra1.x);
        As[buf][(akq + 5) * SAS + arow] = f2tf32(ra1.y);
        As[buf][(akq + 6) * SAS + arow] = f2tf32(ra1.z);
        As[buf][(akq + 7) * SAS + arow] = f2tf32(ra1.w);
        int f0 = tid, f1 = tid + 256;
        int r0 = f0 >> 5, n0 = (f0 & 31) * 4;
        int r1 = f1 >> 5, n1 = (f1 & 31) * 4;
        uint4 b0 = make_uint4(f2tf32(rb0.x), f2tf32(rb0.y), f2tf32(rb0.z), f2tf32(rb0.w));
        uint4 b1 = make_uint4(f2tf32(rb1.x), f2tf32(rb1.y), f2tf32(rb1.z), f2tf32(rb1.w));
        *(uint4*)&Bs[buf][r0 * SAS + n0] = b0;
        *(uint4*)&Bs[buf][r1 * SAS + n1] = b1;
    };

    load_tile(0);
    store_tile(0);
    __syncthreads();

    for (int kt = 0; kt < KT; kt++) {
        bool has_next = (kt + 1 < KT);
        if (has_next) load_tile((kt + 1) << 4);
        int buf = kt & 1;

        #pragma unroll
        for (int ks = 0; ks < 16; ks += 8) {
            uint32_t af[4][4], bf[4][2];
            #pragma unroll
            for (int i = 0; i < 4; i++) {
                int mb = wm0 + i * 16 + grp;
                int kk = ks + tig;
                af[i][0] = As[buf][kk * SAS + mb];
                af[i][1] = As[buf][kk * SAS + mb + 8];
                af[i][2] = As[buf][(kk + 4) * SAS + mb];
                af[i][3] = As[buf][(kk + 4) * SAS + mb + 8];
            }
            #pragma unroll
            for (int j = 0; j < 4; j++) {
                int nb = wn0 + j * 8 + grp;
                int kk = ks + tig;
                bf[j][0] = Bs[buf][kk * SAS + nb];
                bf[j][1] = Bs[buf][(kk + 4) * SAS + nb];
            }
            #pragma unroll
            for (int i = 0; i < 4; i++)
                #pragma unroll
                for (int j = 0; j < 4; j++)
                    mma_tf32(acc[i][j], af[i], bf[j][0], bf[j][1]);
        }
        if (has_next) {
            store_tile((kt + 1) & 1);
            __syncthreads();
        }
    }

    #pragma unroll
    for (int i = 0; i < 4; i++) {
        int r0 = brow + wm0 + i * 16 + grp;
        #pragma unroll
        for (int j = 0; j < 4; j++) {
            int c = bcol + wn0 + j * 8 + tig * 2;
            float b0 = bias ? bias[c] : 0.f;
            float b1 = bias ? bias[c + 1] : 0.f;
            float v0 = acc[i][j][0] + b0, v1 = acc[i][j][1] + b1;
            float v2 = acc[i][j][2] + b0, v3 = acc[i][j][3] + b1;
            if (act) {
                v0 = v0 > 0.f ? v0 : slope * v0;
                v1 = v1 > 0.f ? v1 : slope * v1;
                v2 = v2 > 0.f ? v2 : slope * v2;
                v3 = v3 > 0.f ? v3 : slope * v3;
            }
            if (OUTHALF) {
                __half* Ch = (__half*)C;
                if (r0 < M)     *(__half2*)&Ch[(size_t)r0 * GNC + c]       = __floats2half2_rn(v0, v1);
                if (r0 + 8 < M) *(__half2*)&Ch[(size_t)(r0 + 8) * GNC + c] = __floats2half2_rn(v2, v3);
            } else {
                float* Cf = (float*)C;
                if (r0 < M)     *(float2*)&Cf[(size_t)r0 * GNC + c]       = make_float2(v0, v1);
                if (r0 + 8 < M) *(float2*)&Cf[(size_t)(r0 + 8) * GNC + c] = make_float2(v2, v3);
            }
        }
    }
}

// ---------------- fp16 m16n8k16 GEMM: C[M,512] = act(A[M,K]@B[K,512]+bias), K%32==0 ----------------
#define FSA 20

template <int AHALF, int OUTHALF>
__global__ void __launch_bounds__(256) k_gemm_f16(
    const void* __restrict__ Av, const float* __restrict__ B,
    void* __restrict__ C, int M, int K,
    const float* __restrict__ bias, int act, float slope)
{
    __shared__ __align__(16) uint32_t As[2][128 * FSA];
    __shared__ __align__(16) uint32_t Bs[2][128 * FSA];

    int tid = threadIdx.x;
    int lane = tid & 31, wid = tid >> 5;
    int grp = lane >> 2, tig = lane & 3;
    int wm0 = (wid & 1) * 64, wn0 = (wid >> 1) * 32;
    int brow = blockIdx.y * 128, bcol = blockIdx.x * 128;

    int am = tid >> 1, aq = tid & 1;

    float acc[4][4][4];
    #pragma unroll
    for (int i = 0; i < 4; i++)
        #pragma unroll
        for (int j = 0; j < 4; j++)
            #pragma unroll
            for (int q = 0; q < 4; q++) acc[i][j][q] = 0.f;

    int KT = K >> 5;
    uint32_t ua[8];
    float rb0[8], rb1[8];

    auto load_tile = [&](int k0) {
        if (brow + am < M) {
            if (AHALF) {
                const __half* ap = (const __half*)Av + (size_t)(brow + am) * K + k0 + 16 * aq;
                uint4 u0 = *(const uint4*)ap;
                uint4 u1 = *(const uint4*)(ap + 8);
                ua[0] = u0.x; ua[1] = u0.y; ua[2] = u0.z; ua[3] = u0.w;
                ua[4] = u1.x; ua[5] = u1.y; ua[6] = u1.z; ua[7] = u1.w;
            } else {
                const float* ap = (const float*)Av + (size_t)(brow + am) * K + k0 + 16 * aq;
                #pragma unroll
                for (int j = 0; j < 4; j++) {
                    float4 f = *(const float4*)(ap + 4 * j);
                    __half2 h0 = __floats2half2_rn(f.x, f.y);
                    __half2 h1 = __floats2half2_rn(f.z, f.w);
                    ua[2 * j]     = *(uint32_t*)&h0;
                    ua[2 * j + 1] = *(uint32_t*)&h1;
                }
            }
        } else {
            #pragma unroll
            for (int j = 0; j < 8; j++) ua[j] = 0u;
        }
        #pragma unroll
        for (int i = 0; i < 8; i++) {
            int idx = tid + 256 * i;
            int n = idx & 127, kh = idx >> 7;
            const float* bp = B + (size_t)(k0 + 2 * kh) * GNC + bcol + n;
            rb0[i] = bp[0];
            rb1[i] = bp[GNC];
        }
    };
    auto store_tile = [&](int buf) {
        #pragma unroll
        for (int j = 0; j < 8; j++) As[buf][am * FSA + 8 * aq + j] = ua[j];
        #pragma unroll
        for (int i = 0; i < 8; i++) {
            int idx = tid + 256 * i;
            int n = idx & 127, kh = idx >> 7;
            __half2 h = __floats2half2_rn(rb0[i], rb1[i]);
            Bs[buf][n * FSA + kh] = *(uint32_t*)&h;
        }
    };

    load_tile(0);
    store_tile(0);
    __syncthreads();

    for (int kt = 0; kt < KT; kt++) {
        bool has_next = (kt + 1 < KT);
        if (has_next) load_tile((kt + 1) << 5);
        int buf = kt & 1;

        #pragma unroll
        for (int ks = 0; ks < 2; ks++) {
            uint32_t af[4][4], bf[4][2];
            #pragma unroll
            for (int i = 0; i < 4; i++) {
                int m = wm0 + i * 16 + grp;
                int b0 = m * FSA + ks * 8;
                int b1 = (m + 8) * FSA + ks * 8;
                af[i][0] = As[buf][b0 + tig];
                af[i][1] = As[buf][b1 + tig];
                af[i][2] = As[buf][b0 + tig + 4];
                af[i][3] = As[buf][b1 + tig + 4];
            }
            #pragma unroll
            for (int j = 0; j < 4; j++) {
                int n = wn0 + j * 8 + grp;
                bf[j][0] = Bs[buf][n * FSA + ks * 8 + tig];
                bf[j][1] = Bs[buf][n * FSA + ks * 8 + tig + 4];
            }
            #pragma unroll
            for (int i = 0; i < 4; i++)
                #pragma unroll
                for (int j = 0; j < 4; j++)
                    mma_f16(acc[i][j], af[i], bf[j][0], bf[j][1]);
        }
        if (has_next) {
            store_tile((kt + 1) & 1);
            __syncthreads();
        }
    }

    #pragma unroll
    for (int i = 0; i < 4; i++) {
        int r0 = brow + wm0 + i * 16 + grp;
        #pragma unroll
        for (int j = 0; j < 4; j++) {
            int c = bcol + wn0 + j * 8 + tig * 2;
            float b0 = bias ? bias[c] : 0.f;
            float b1 = bias ? bias[c + 1] : 0.f;
            float v0 = acc[i][j][0] + b0, v1 = acc[i][j][1] + b1;
            float v2 = acc[i][j][2] + b0, v3 = acc[i][j][3] + b1;
            if (act) {
                v0 = v0 > 0.f ? v0 : slope * v0;
                v1 = v1 > 0.f ? v1 : slope * v1;
                v2 = v2 > 0.f ? v2 : slope * v2;
                v3 = v3 > 0.f ? v3 : slope * v3;
            }
            if (OUTHALF) {
                __half* Ch = (__half*)C;
                if (r0 < M)     *(__half2*)&Ch[(size_t)r0 * GNC + c]       = __floats2half2_rn(v0, v1);
                if (r0 + 8 < M) *(__half2*)&Ch[(size_t)(r0 + 8) * GNC + c] = __floats2half2_rn(v2, v3);
            } else {
                float* Cf = (float*)C;
                if (r0 < M)     *(float2*)&Cf[(size_t)r0 * GNC + c]       = make_float2(v0, v1);
                if (r0 + 8 < M) *(float2*)&Cf[(size_t)(r0 + 8) * GNC + c] = make_float2(v2, v3);
            }
        }
    }
}

// ---------------- layer-1 aggregation (unroll-2): streaming attention, gathered xh1h ----------------
__global__ void __launch_bounds__(256) k_agg1(
    const float* __restrict__ bias, const float* __restrict__ alphap)
{
    int g = blockIdx.x * blockDim.x + threadIdx.x;
    int v = g >> 5;
    if (v >= NN) return;
    int lane = g & 31;
    float2 acc[8];
    #pragma unroll
    for (int k = 0; k < 8; k++) acc[k] = make_float2(0.f, 0.f);
    int lo = g_ipd[v], hi = g_ipd[v + 1];
    int p = lo;
    for (; p + 1 < hi; p += 2) {
        int s0 = g_src_of_pd[p];
        int s1 = g_src_of_pd[p + 1];
        float2 a0 = __half22float2(g_ew1h[(size_t)p * 32 + lane]);
        float2 a1 = __half22float2(g_ew1h[(size_t)(p + 1) * 32 + lane]);
        const __half2* x0 = g_xh1h + (size_t)s0 * 256;
        const __half2* x1 = g_xh1h + (size_t)s1 * 256;
        #pragma unroll
        for (int k = 0; k < 8; k++) {
            float2 f0 = __half22float2(x0[lane + 32 * k]);
            float2 f1 = __half22float2(x1[lane + 32 * k]);
            acc[k].x += a0.x * f0.x + a1.x * f1.x;
            acc[k].y += a0.y * f0.y + a1.y * f1.y;
        }
    }
    if (p < hi) {
        int s0 = g_src_of_pd[p];
        float2 a0 = __half22float2(g_ew1h[(size_t)p * 32 + lane]);
        const __half2* x0 = g_xh1h + (size_t)s0 * 256;
        #pragma unroll
        for (int k = 0; k < 8; k++) {
            float2 f0 = __half22float2(x0[lane + 32 * k]);
            acc[k].x += a0.x * f0.x;
            acc[k].y += a0.y * f0.y;
        }
    }

    float al = *alphap;
    const __half2* pr = g_p1h + (size_t)v * 256;
    __half2* hw = g_hh + (size_t)v * 256;
    #pragma unroll
    for (int k = 0; k < 8; k++) {
        int j = 2 * lane + 64 * k;
        float2 pv = __half22float2(pr[lane + 32 * k]);
        float o0 = fmaxf(acc[k].x + bias[j]     + al * pv.x, 0.f);
        float o1 = fmaxf(acc[k].y + bias[j + 1] + al * pv.y, 0.f);
        hw[lane + 32 * k] = __floats2half2_rn(o0, o1);
    }
}

// ---------------- xh2 = h @ W_src2  ([N,512]x[512,16], h fp16) ----------------
__global__ void __launch_bounds__(256) k_xh2(const float* __restrict__ W) {
    __shared__ float sW[512 * 16];
    int tid = threadIdx.x;
    for (int i = tid; i < 512 * 16; i += 256) sW[i] = W[i];
    __syncthreads();
    int g = blockIdx.x * 256 + tid;
    int v = g >> 4, c = g & 15;
    if (v >= NN) return;
    const __half2* hr = g_hh + (size_t)v * 256;
    float acc = 0.f;
    #pragma unroll 4
    for (int i = 0; i < 256; i++) {
        float2 f = __half22float2(hr[i]);
        int j = 2 * (i & 31) + 64 * (i >> 5);
        acc += f.x * sW[j * 16 + c] + f.y * sW[(j + 1) * 16 + c];
    }
    g_xh2[g] = acc;
}

// ---------------- layer-2 aggregation + bias + alpha*p2 + log_softmax ----------------
__global__ void __launch_bounds__(256) k_agg2(
    const float* __restrict__ bias2, const float* __restrict__ alphap,
    float* __restrict__ out)
{
    int g = blockIdx.x * 256 + threadIdx.x;
    int v = g >> 4, c = g & 15;
    float acc = 0.f;
    int lo = g_ipd[v], hi = g_ipd[v + 1];
    for (int p = lo; p < hi; p++) {
        int s = g_src_of_pd[p];
        acc += __half2float(g_ew2d[(size_t)p * 16 + c]) * g_xh2[s * 16 + c];
    }
    float o = acc + bias2[c] + (*alphap) * g_p2[g];
    float m = o;
    #pragma unroll
    for (int d = 8; d > 0; d >>= 1) m = fmaxf(m, __shfl_xor_sync(0xffffffffu, m, d, 16));
    float se = __expf(o - m);
    #pragma unroll
    for (int d = 8; d > 0; d >>= 1) se += __shfl_xor_sync(0xffffffffu, se, d, 16);
    out[g] = o - m - logf(se);
}

// ---------------- stream/event context ----------------
struct HxCtx {
    cudaStream_t sB, sC;
    cudaEvent_t ev0, evCSR, evB, evC;
    HxCtx() {
        cudaStreamCreateWithFlags(&sB, cudaStreamNonBlocking);
        cudaStreamCreateWithFlags(&sC, cudaStreamNonBlocking);
        cudaEventCreateWithFlags(&ev0,   cudaEventDisableTiming);
        cudaEventCreateWithFlags(&evCSR, cudaEventDisableTiming);
        cudaEventCreateWithFlags(&evB,   cudaEventDisableTiming);
        cudaEventCreateWithFlags(&evC,   cudaEventDisableTiming);
        cudaFuncSetAttribute(k_emlp1, cudaFuncAttributeMaxDynamicSharedMemorySize, EMLP_SMEM);
    }
};
static HxCtx g_ctx;

// ---------------- host launch ----------------
extern "C" void kernel_launch(void* const* d_in, const int* in_sizes, int n_in,
                              void* d_out, int out_size)
{
    const float* x       = (const float*)d_in[0];
    const int*   ei      = (const int*)  d_in[1];
    const float* alpha   = (const float*)d_in[2];
    const float* k_ricci = (const float*)d_in[3];
    const float* e_poinc = (const float*)d_in[4];
    const float* W1      = (const float*)d_in[5];
    const float* h1w1    = (const float*)d_in[6];
    const float* h1w2    = (const float*)d_in[7];
    const float* h1b2    = (const float*)d_in[8];
    const float* p1w1    = (const float*)d_in[9];
    const float* p1w2    = (const float*)d_in[10];
    const float* p1b2    = (const float*)d_in[11];
    const float* bias1   = (const float*)d_in[12];
    const float* W2      = (const float*)d_in[13];
    const float* h2w1    = (const float*)d_in[14];
    const float* h2w2    = (const float*)d_in[15];
    const float* h2b2    = (const float*)d_in[16];
    const float* p2w1    = (const float*)d_in[17];
    const float* p2w2    = (const float*)d_in[18];
    const float* p2b2    = (const float*)d_in[19];
    const float* bias2   = (const float*)d_in[20];
    float* out = (float*)d_out;

    void *p_xh1h, *p_t1h, *p_p1h, *p_ew1l, *p_ew2h, *p_p2;
    int *p_eid_src;
    cudaGetSymbolAddress(&p_xh1h, g_xh1h);
    cudaGetSymbolAddress(&p_t1h,  g_t1h);
    cudaGetSymbolAddress(&p_p1h,  g_p1h);
    cudaGetSymbolAddress(&p_ew1l, g_ew1l);
    cudaGetSymbolAddress(&p_ew2h, g_ew2h);
    cudaGetSymbolAddress(&p_p2,   g_p2);
    cudaGetSymbolAddress((void**)&p_eid_src, g_eid_src);

    cudaStream_t sB = g_ctx.sB, sC = g_ctx.sC;

    // fork
    cudaEventRecord(g_ctx.ev0, 0);
    cudaStreamWaitEvent(sB, g_ctx.ev0, 0);
    cudaStreamWaitEvent(sC, g_ctx.ev0, 0);

    // ---- stream B: CSR + layer-1 attention (the agg1 prerequisites ONLY) ----
    k_zero<<<(NN + 255) / 256, 256, 0, sB>>>();
    k_count<<<(ET + 255) / 256, 256, 0, sB>>>(ei);
    k_scan<<<2, 1024, 0, sB>>>();
    k_fill<<<(ET + 255) / 256, 256, 0, sB>>>(ei);
    cudaEventRecord(g_ctx.evCSR, sB);
    k_emlp1<<<(ET + 127) / 128, 256, EMLP_SMEM, sB>>>(k_ricci, h1w1, h1w2, h1b2, (__half2*)p_ew1l);
    k_softmax1<<<(NN * 32) / 256, 256, 0, sB>>>();
    cudaEventRecord(g_ctx.evB, sB);

    // ---- stream C: layer-2 attention + p2 (only needed by agg2; overlaps with agg1/xh2) ----
    cudaStreamWaitEvent(sC, g_ctx.evCSR, 0);
    k_mlp<16, 16, 16, 128, false, true ><<<(ET + 127) / 128, 128, 0, sC>>>(k_ricci, h2w1, h2w2, h2b2, p_ew2h, ET, p_eid_src);
    k_softmax2<<<(NN * 16) / 256, 256, 0, sC>>>();
    k_mlp<16, 16, 16, 128, true,  false><<<(NN + 127) / 128, 128, 0, sC>>>(e_poinc, p2w1, p2w2, p2b2, p_p2, NN, nullptr);
    cudaEventRecord(g_ctx.evC, sC);

    // ---- default stream: dense chain (fp16 HMMA for the two big GEMMs) ----
    dim3 gg(512 / 128, (NN + 127) / 128);
    k_gemm_f16 <0, 1><<<gg, 256>>>(x,       W1,   p_xh1h, NN, 128, nullptr, 0, 0.f);
    k_gemm_tf32<0, 1><<<gg, 256>>>(e_poinc, p1w1, p_t1h,  NN, 16,  nullptr, 1, 0.2f);
    k_gemm_f16 <1, 1><<<gg, 256>>>(p_t1h,   p1w2, p_p1h,  NN, 512, p1b2,    1, 0.01f);

    // join for agg1 (needs softmax1 + xh1 + p1)
    cudaStreamWaitEvent(0, g_ctx.evB, 0);
    k_agg1<<<(NN * 32) / 256, 256>>>(bias1, alpha);
    k_xh2<<<(NN * 16) / 256, 256>>>(W2);

    // join for agg2 (needs xh2 + ew2d + p2)
    cudaStreamWaitEvent(0, g_ctx.evC, 0);
    k_agg2<<<(NN * 16) / 256, 256>>>(bias2, alpha, out);
}